// round 6
// baseline (speedup 1.0000x reference)
#include <cuda_runtime.h>
#include <cuda_fp16.h>
#include <cstdint>

// Problem dims
static constexpr int T_ = 512, B_ = 32, I_ = 512, H_ = 512;
static constexpr int M_  = T_ * B_;   // 16384 (GEMM M)
static constexpr int N3_ = 3 * H_;    // 1536  (GEMM N)
static constexpr int K_  = I_;        // 512   (GEMM K)

// GEMM tiling (mma.sync m16n8k16, baseline sm_103 features only — NO tcgen05)
static constexpr int TM = 128, TN = 128, TK = 64;
static constexpr int NCH  = K_ / TK;        // 8 K-tiles
static constexpr int NSTG = 3;
// Stage: Ah 16K | Al 16K | Bh 16K | Bl 16K  (each 128 rows x 128B swizzled)
static constexpr int STAGE = 65536;
static constexpr int SMEM_TOTAL = NSTG * STAGE;   // 196608

// ---------------- scratch (device globals; no allocation allowed) ----------------
__device__ __align__(256) __half g_xh[(size_t)M_ * K_];
__device__ __align__(256) __half g_xl[(size_t)M_ * K_];
__device__ __align__(256) __half g_wh[(size_t)N3_ * K_];
__device__ __align__(256) __half g_wl[(size_t)N3_ * K_];
__device__ __align__(256) float  g_gx[(size_t)M_ * N3_];

// ---------------- PTX helpers (all baseline sm_80+ features) ----------------
__device__ __forceinline__ uint32_t smem_u32(const void* p) {
    return (uint32_t)__cvta_generic_to_shared(p);
}
__device__ __forceinline__ void cp16(uint32_t s, const void* g) {
    asm volatile("cp.async.cg.shared.global [%0], [%1], 16;" :: "r"(s), "l"(g));
}
__device__ __forceinline__ void ldsm4(uint32_t& r0, uint32_t& r1, uint32_t& r2, uint32_t& r3,
                                      uint32_t a) {
    asm volatile("ldmatrix.sync.aligned.m8n8.x4.shared.b16 {%0,%1,%2,%3}, [%4];"
                 : "=r"(r0), "=r"(r1), "=r"(r2), "=r"(r3) : "r"(a));
}
__device__ __forceinline__ void mma16816(float* c, const uint32_t* a, const uint32_t* b) {
    asm volatile(
        "mma.sync.aligned.m16n8k16.row.col.f32.f16.f16.f32 "
        "{%0,%1,%2,%3}, {%4,%5,%6,%7}, {%8,%9}, {%0,%1,%2,%3};"
        : "+f"(c[0]), "+f"(c[1]), "+f"(c[2]), "+f"(c[3])
        : "r"(a[0]), "r"(a[1]), "r"(a[2]), "r"(a[3]), "r"(b[0]), "r"(b[1]));
}

// ---------------- prep: split fp32 -> fp16 hi + lo ----------------
__device__ __forceinline__ void split1(float v, __half& h, __half& l) {
    h = __float2half_rn(v);
    l = __float2half_rn(v - __half2float(h));
}

__global__ void split_x_kernel(const float* __restrict__ src) {
    int i = blockIdx.x * blockDim.x + threadIdx.x;          // one float4 per thread
    float4 v = ((const float4*)src)[i];
    __half h0, h1, h2, h3, l0, l1, l2, l3;
    split1(v.x, h0, l0); split1(v.y, h1, l1); split1(v.z, h2, l2); split1(v.w, h3, l3);
    __half2* ph = (__half2*)g_xh;
    __half2* pl = (__half2*)g_xl;
    ph[2 * i]     = __halves2half2(h0, h1);
    ph[2 * i + 1] = __halves2half2(h2, h3);
    pl[2 * i]     = __halves2half2(l0, l1);
    pl[2 * i + 1] = __halves2half2(l2, l3);
}

__global__ void split_w_kernel(const float* __restrict__ src) {
    int i = blockIdx.x * blockDim.x + threadIdx.x;
    float4 v = ((const float4*)src)[i];
    __half h0, h1, h2, h3, l0, l1, l2, l3;
    split1(v.x, h0, l0); split1(v.y, h1, l1); split1(v.z, h2, l2); split1(v.w, h3, l3);
    __half2* ph = (__half2*)g_wh;
    __half2* pl = (__half2*)g_wl;
    ph[2 * i]     = __halves2half2(h0, h1);
    ph[2 * i + 1] = __halves2half2(h2, h3);
    pl[2 * i]     = __halves2half2(l0, l1);
    pl[2 * i + 1] = __halves2half2(l2, l3);
}

// ---------------- GEMM: gx = Xsplit @ Wsplit^T via mma.sync (3-product fp16) ------
// Smem row layout: 64 fp16 = 128B per row; 16B chunk j stored at (j ^ (row&7))*16.
__device__ __forceinline__ void load_quarter(uint32_t dst, const __half* __restrict__ g,
                                             int row0, int k0, int tid) {
    // 128 rows x 8 chunks of 16B = 1024 cp16, 256 threads -> 4 each
    #pragma unroll
    for (int u = 0; u < 4; u++) {
        int i = tid + u * 256;
        int r = i >> 3, j = i & 7;
        cp16(dst + (uint32_t)(r * 128 + ((j ^ (r & 7)) << 4)),
             g + (size_t)(row0 + r) * K_ + k0 + j * 8);
    }
}

__device__ __forceinline__ void load_stage(uint32_t st, int m0, int n0, int k0, int tid) {
    load_quarter(st,          g_xh, m0, k0, tid);
    load_quarter(st + 16384u, g_xl, m0, k0, tid);
    load_quarter(st + 32768u, g_wh, n0, k0, tid);
    load_quarter(st + 49152u, g_wl, n0, k0, tid);
    asm volatile("cp.async.commit_group;" ::: "memory");
}

__global__ __launch_bounds__(256, 1) void gemm_kernel() {
    extern __shared__ __align__(1024) char smem[];
    uint32_t sb = smem_u32(smem);
    int tid = threadIdx.x, lane = tid & 31, wid = tid >> 5;
    int wm = wid & 1, wn = wid >> 1;          // 2 x 4 warp grid; warp tile 64m x 32n
    int m0 = blockIdx.x * TM, n0 = blockIdx.y * TN;
    int g = lane >> 3;                         // ldmatrix lane group

    float acc[4][4][4];
    #pragma unroll
    for (int a = 0; a < 4; a++)
        #pragma unroll
        for (int b = 0; b < 4; b++)
            #pragma unroll
            for (int c = 0; c < 4; c++) acc[a][b][c] = 0.f;

    load_stage(sb,         m0, n0, 0,  tid);
    load_stage(sb + STAGE, m0, n0, TK, tid);

    for (int cc = 0; cc < NCH; cc++) {
        if (cc < NCH - 1) asm volatile("cp.async.wait_group 1;" ::: "memory");
        else              asm volatile("cp.async.wait_group 0;" ::: "memory");
        __syncthreads();

        uint32_t st = sb + (uint32_t)(cc % 3) * STAGE;
        #pragma unroll
        for (int ks = 0; ks < 4; ks++) {
            // A fragments (hi, lo): 4 m-frags of 16 rows each
            uint32_t ah[4][4], al[4][4];
            #pragma unroll
            for (int mi = 0; mi < 4; mi++) {
                int row = wm * 64 + mi * 16 + ((g & 1) << 3) + (lane & 7);
                uint32_t off = (uint32_t)(row * 128 +
                                (((ks * 2 + (g >> 1)) ^ (row & 7)) << 4));
                ldsm4(ah[mi][0], ah[mi][1], ah[mi][2], ah[mi][3], st + off);
                ldsm4(al[mi][0], al[mi][1], al[mi][2], al[mi][3], st + 16384u + off);
            }
            // B fragments (hi, lo): 4 n-frags of 8, loaded in pairs via x4
            uint32_t bh[4][2], bl[4][2];
            #pragma unroll
            for (int p = 0; p < 2; p++) {
                int row = wn * 32 + p * 16 + ((g >> 1) << 3) + (lane & 7);
                uint32_t off = (uint32_t)(row * 128 +
                                (((ks * 2 + (g & 1)) ^ (row & 7)) << 4));
                uint32_t r0, r1, r2, r3;
                ldsm4(r0, r1, r2, r3, st + 32768u + off);
                bh[2 * p][0] = r0; bh[2 * p][1] = r1;
                bh[2 * p + 1][0] = r2; bh[2 * p + 1][1] = r3;
                ldsm4(r0, r1, r2, r3, st + 49152u + off);
                bl[2 * p][0] = r0; bl[2 * p][1] = r1;
                bl[2 * p + 1][0] = r2; bl[2 * p + 1][1] = r3;
            }
            // 3-product split: ah*bh + ah*bl + al*bh  (lo*lo dropped, ~2^-22)
            #pragma unroll
            for (int mi = 0; mi < 4; mi++)
                #pragma unroll
                for (int ni = 0; ni < 4; ni++) {
                    mma16816(acc[mi][ni], ah[mi], bh[ni]);
                    mma16816(acc[mi][ni], ah[mi], bl[ni]);
                    mma16816(acc[mi][ni], al[mi], bh[ni]);
                }
        }
        __syncthreads();
        if (cc + 2 < NCH)
            load_stage(sb + (uint32_t)((cc + 2) % 3) * STAGE, m0, n0, (cc + 2) * TK, tid);
    }

    // Epilogue: direct float2 stores to g_gx
    #pragma unroll
    for (int mi = 0; mi < 4; mi++) {
        int row = m0 + wm * 64 + mi * 16 + (lane >> 2);
        #pragma unroll
        for (int ni = 0; ni < 4; ni++) {
            int col = n0 + wn * 32 + ni * 8 + 2 * (lane & 3);
            *(float2*)(g_gx + (size_t)row * N3_ + col) =
                make_float2(acc[mi][ni][0], acc[mi][ni][1]);
            *(float2*)(g_gx + (size_t)(row + 8) * N3_ + col) =
                make_float2(acc[mi][ni][2], acc[mi][ni][3]);
        }
    }
}

// ---------------- IndGRU recurrence: one thread per (b, h) channel ----------------
__device__ __forceinline__ float sigm_f(float x) {
    return __fdividef(1.f, 1.f + __expf(-x));
}
__device__ __forceinline__ float tanh_f(float x) {
    float e = __expf(2.f * x);
    return 1.f - __fdividef(2.f, e + 1.f);
}

__global__ __launch_bounds__(128) void recur_kernel(const float* __restrict__ h0,
                                                    const float* __restrict__ whh,
                                                    float* __restrict__ out) {
    int idx = blockIdx.x * 128 + threadIdx.x;   // 0..16383 = b*512 + h
    int h = idx & (H_ - 1);
    int b = idx >> 9;
    float hv = h0[idx];
    float wr = whh[h], wz = whh[H_ + h], wn = whh[2 * H_ + h];
    const float* gp = g_gx + (size_t)b * N3_ + h;   // row t*32+b, col h
    float* op = out + idx;
    #pragma unroll 4
    for (int t = 0; t < T_; t++) {
        float gr = __ldg(gp);
        float gz = __ldg(gp + H_);
        float gn = __ldg(gp + 2 * H_);
        float r  = sigm_f(fmaf(wr, hv, gr));
        float z  = sigm_f(fmaf(wz, hv, gz));
        float nn = tanh_f(fmaf(r, wn * hv, gn));
        hv = fmaf(z, hv - nn, nn);               // (1-z)*n + z*h
        *op = hv;
        gp += B_ * N3_;
        op += B_ * H_;
    }
    out[(size_t)T_ * B_ * H_ + idx] = hv;         // h_last
}

// ---------------- launch ----------------
extern "C" void kernel_launch(void* const* d_in, const int* in_sizes, int n_in,
                              void* d_out, int out_size) {
    const float* x   = (const float*)d_in[0];   // (T, B, I)
    const float* h0  = (const float*)d_in[1];   // (B, H)
    const float* Wih = (const float*)d_in[2];   // (3H, I)
    const float* whh = (const float*)d_in[3];   // (3, H)
    float* out = (float*)d_out;                 // (T,B,H) then (1,B,H)

    (void)in_sizes; (void)n_in; (void)out_size;

    cudaFuncSetAttribute(gemm_kernel, cudaFuncAttributeMaxDynamicSharedMemorySize, SMEM_TOTAL);

    split_x_kernel<<<(M_ * K_ / 4) / 256, 256>>>(x);
    split_w_kernel<<<(N3_ * K_ / 4) / 256, 256>>>(Wih);
    gemm_kernel<<<dim3(M_ / TM, N3_ / TN), 256, SMEM_TOTAL>>>();
    recur_kernel<<<(B_ * H_) / 128, 128>>>(h0, whh, out);
}

// round 7
// speedup vs baseline: 1.2423x; 1.2423x over previous
#include <cuda_runtime.h>
#include <cuda_fp16.h>
#include <cstdint>

// Problem dims
static constexpr int T_ = 512, B_ = 32, I_ = 512, H_ = 512;
static constexpr int M_  = T_ * B_;   // 16384 (GEMM M)
static constexpr int N3_ = 3 * H_;    // 1536  (GEMM N)
static constexpr int K_  = I_;        // 512   (GEMM K)

// GEMM tiling (mma.sync m16n8k16, baseline sm_103 features only — NO tcgen05)
static constexpr int TM = 128, TN = 128, TK = 64;
static constexpr int NCH  = K_ / TK;        // 8 K-tiles
static constexpr int NSTG = 3;
// Stage: Ah 16K | Al 16K | Bh 16K | Bl 16K  (each 128 rows x 128B swizzled)
static constexpr int STAGE = 65536;
static constexpr int SMEM_TOTAL = NSTG * STAGE;   // 196608

// ---------------- scratch (device globals; no allocation allowed) ----------------
__device__ __align__(256) __half g_xh[(size_t)M_ * K_];
__device__ __align__(256) __half g_xl[(size_t)M_ * K_];
__device__ __align__(256) __half g_wh[(size_t)N3_ * K_];
__device__ __align__(256) __half g_wl[(size_t)N3_ * K_];
__device__ __align__(256) float  g_gx[(size_t)M_ * N3_];

// ---------------- PTX helpers (all baseline sm_80+ features) ----------------
__device__ __forceinline__ uint32_t smem_u32(const void* p) {
    return (uint32_t)__cvta_generic_to_shared(p);
}
__device__ __forceinline__ void cp16(uint32_t s, const void* g) {
    asm volatile("cp.async.cg.shared.global [%0], [%1], 16;" :: "r"(s), "l"(g));
}
__device__ __forceinline__ void ldsm4(uint32_t& r0, uint32_t& r1, uint32_t& r2, uint32_t& r3,
                                      uint32_t a) {
    asm volatile("ldmatrix.sync.aligned.m8n8.x4.shared.b16 {%0,%1,%2,%3}, [%4];"
                 : "=r"(r0), "=r"(r1), "=r"(r2), "=r"(r3) : "r"(a));
}
__device__ __forceinline__ void mma16816(float* c, const uint32_t* a, const uint32_t* b) {
    asm volatile(
        "mma.sync.aligned.m16n8k16.row.col.f32.f16.f16.f32 "
        "{%0,%1,%2,%3}, {%4,%5,%6,%7}, {%8,%9}, {%0,%1,%2,%3};"
        : "+f"(c[0]), "+f"(c[1]), "+f"(c[2]), "+f"(c[3])
        : "r"(a[0]), "r"(a[1]), "r"(a[2]), "r"(a[3]), "r"(b[0]), "r"(b[1]));
}
__device__ __forceinline__ float ex2f(float x) {
    float y; asm("ex2.approx.f32 %0, %1;" : "=f"(y) : "f"(x)); return y;
}
__device__ __forceinline__ float rcpf(float x) {
    float y; asm("rcp.approx.f32 %0, %1;" : "=f"(y) : "f"(x)); return y;
}

// ---------------- prep: split fp32 -> fp16 hi + lo ----------------
__device__ __forceinline__ void split1(float v, __half& h, __half& l) {
    h = __float2half_rn(v);
    l = __float2half_rn(v - __half2float(h));
}

__global__ void split_x_kernel(const float* __restrict__ src) {
    int i = blockIdx.x * blockDim.x + threadIdx.x;          // one float4 per thread
    float4 v = ((const float4*)src)[i];
    __half h0, h1, h2, h3, l0, l1, l2, l3;
    split1(v.x, h0, l0); split1(v.y, h1, l1); split1(v.z, h2, l2); split1(v.w, h3, l3);
    __half2* ph = (__half2*)g_xh;
    __half2* pl = (__half2*)g_xl;
    ph[2 * i]     = __halves2half2(h0, h1);
    ph[2 * i + 1] = __halves2half2(h2, h3);
    pl[2 * i]     = __halves2half2(l0, l1);
    pl[2 * i + 1] = __halves2half2(l2, l3);
}

__global__ void split_w_kernel(const float* __restrict__ src) {
    int i = blockIdx.x * blockDim.x + threadIdx.x;
    float4 v = ((const float4*)src)[i];
    __half h0, h1, h2, h3, l0, l1, l2, l3;
    split1(v.x, h0, l0); split1(v.y, h1, l1); split1(v.z, h2, l2); split1(v.w, h3, l3);
    __half2* ph = (__half2*)g_wh;
    __half2* pl = (__half2*)g_wl;
    ph[2 * i]     = __halves2half2(h0, h1);
    ph[2 * i + 1] = __halves2half2(h2, h3);
    pl[2 * i]     = __halves2half2(l0, l1);
    pl[2 * i + 1] = __halves2half2(l2, l3);
}

// ---------------- GEMM: gx = Xsplit @ Wsplit^T via mma.sync (3-product fp16) ------
// Smem row layout: 64 fp16 = 128B per row; 16B chunk j stored at (j ^ (row&7))*16.
__device__ __forceinline__ void load_quarter(uint32_t dst, const __half* __restrict__ g,
                                             int row0, int k0, int tid) {
    // 128 rows x 8 chunks of 16B = 1024 cp16, 256 threads -> 4 each
    #pragma unroll
    for (int u = 0; u < 4; u++) {
        int i = tid + u * 256;
        int r = i >> 3, j = i & 7;
        cp16(dst + (uint32_t)(r * 128 + ((j ^ (r & 7)) << 4)),
             g + (size_t)(row0 + r) * K_ + k0 + j * 8);
    }
}

__device__ __forceinline__ void load_stage(uint32_t st, int m0, int n0, int k0, int tid) {
    load_quarter(st,          g_xh, m0, k0, tid);
    load_quarter(st + 16384u, g_xl, m0, k0, tid);
    load_quarter(st + 32768u, g_wh, n0, k0, tid);
    load_quarter(st + 49152u, g_wl, n0, k0, tid);
    asm volatile("cp.async.commit_group;" ::: "memory");
}

__global__ __launch_bounds__(256, 1) void gemm_kernel() {
    extern __shared__ __align__(1024) char smem[];
    uint32_t sb = smem_u32(smem);
    int tid = threadIdx.x, lane = tid & 31, wid = tid >> 5;
    int wm = wid & 1, wn = wid >> 1;          // 2 x 4 warp grid; warp tile 64m x 32n
    int m0 = blockIdx.x * TM, n0 = blockIdx.y * TN;
    int g = lane >> 3;                         // ldmatrix lane group

    float acc[4][4][4];
    #pragma unroll
    for (int a = 0; a < 4; a++)
        #pragma unroll
        for (int b = 0; b < 4; b++)
            #pragma unroll
            for (int c = 0; c < 4; c++) acc[a][b][c] = 0.f;

    load_stage(sb,         m0, n0, 0,  tid);
    load_stage(sb + STAGE, m0, n0, TK, tid);

    for (int cc = 0; cc < NCH; cc++) {
        if (cc < NCH - 1) asm volatile("cp.async.wait_group 1;" ::: "memory");
        else              asm volatile("cp.async.wait_group 0;" ::: "memory");
        __syncthreads();

        uint32_t st = sb + (uint32_t)(cc % 3) * STAGE;
        #pragma unroll
        for (int ks = 0; ks < 4; ks++) {
            // A fragments (hi, lo): 4 m-frags of 16 rows each
            uint32_t ah[4][4], al[4][4];
            #pragma unroll
            for (int mi = 0; mi < 4; mi++) {
                int row = wm * 64 + mi * 16 + ((g & 1) << 3) + (lane & 7);
                uint32_t off = (uint32_t)(row * 128 +
                                (((ks * 2 + (g >> 1)) ^ (row & 7)) << 4));
                ldsm4(ah[mi][0], ah[mi][1], ah[mi][2], ah[mi][3], st + off);
                ldsm4(al[mi][0], al[mi][1], al[mi][2], al[mi][3], st + 16384u + off);
            }
            // B fragments (hi, lo): 4 n-frags of 8, loaded in pairs via x4
            uint32_t bh[4][2], bl[4][2];
            #pragma unroll
            for (int p = 0; p < 2; p++) {
                int row = wn * 32 + p * 16 + ((g >> 1) << 3) + (lane & 7);
                uint32_t off = (uint32_t)(row * 128 +
                                (((ks * 2 + (g & 1)) ^ (row & 7)) << 4));
                uint32_t r0, r1, r2, r3;
                ldsm4(r0, r1, r2, r3, st + 32768u + off);
                bh[2 * p][0] = r0; bh[2 * p][1] = r1;
                bh[2 * p + 1][0] = r2; bh[2 * p + 1][1] = r3;
                ldsm4(r0, r1, r2, r3, st + 49152u + off);
                bl[2 * p][0] = r0; bl[2 * p][1] = r1;
                bl[2 * p + 1][0] = r2; bl[2 * p + 1][1] = r3;
            }
            // 3-product split: ah*bh + ah*bl + al*bh  (lo*lo dropped, ~2^-22)
            #pragma unroll
            for (int mi = 0; mi < 4; mi++)
                #pragma unroll
                for (int ni = 0; ni < 4; ni++) {
                    mma16816(acc[mi][ni], ah[mi], bh[ni]);
                    mma16816(acc[mi][ni], ah[mi], bl[ni]);
                    mma16816(acc[mi][ni], al[mi], bh[ni]);
                }
        }
        __syncthreads();
        if (cc + 2 < NCH)
            load_stage(sb + (uint32_t)((cc + 2) % 3) * STAGE, m0, n0, (cc + 2) * TK, tid);
    }

    // Epilogue: direct float2 stores to g_gx
    #pragma unroll
    for (int mi = 0; mi < 4; mi++) {
        int row = m0 + wm * 64 + mi * 16 + (lane >> 2);
        #pragma unroll
        for (int ni = 0; ni < 4; ni++) {
            int col = n0 + wn * 32 + ni * 8 + 2 * (lane & 3);
            *(float2*)(g_gx + (size_t)row * N3_ + col) =
                make_float2(acc[mi][ni][0], acc[mi][ni][1]);
            *(float2*)(g_gx + (size_t)(row + 8) * N3_ + col) =
                make_float2(acc[mi][ni][2], acc[mi][ni][3]);
        }
    }
}

// ---------------- IndGRU recurrence ----------------
// One thread per (b, h) channel. Software-pipelined register prefetch (D=8
// timesteps, double buffered) fully hides DRAM latency behind the serial
// dependency chain. Activations use raw ex2/rcp with log2e folded into the
// per-channel weights and per-element gate scaling (off the critical path):
//   r = rcp(1 + ex2(wr'*h + gr'))            wr' = -log2e*wr, gr' = -log2e*gr
//   q = rcp(1 + ex2(gn' + r*(wn'*h)))        wn' = 2log2e*wn, gn' = 2log2e*gn
//   h' = (1-z)*(1-2q) + z*h = fma(-2(1-z), q, fma(z, h, 1-z))
// Critical path per step ~84 cyc.
__global__ __launch_bounds__(128) void recur_kernel(const float* __restrict__ h0,
                                                    const float* __restrict__ whh,
                                                    float* __restrict__ out) {
    constexpr float L2E = 1.4426950408889634f;
    constexpr int   D   = 8;                       // prefetch depth (timesteps)
    constexpr int   STRIDE = B_ * N3_;             // floats per timestep in g_gx

    int idx = blockIdx.x * 128 + threadIdx.x;      // 0..16383 = b*512 + h
    int h = idx & (H_ - 1);
    int b = idx >> 9;

    float hv   = h0[idx];
    float wrp  = -L2E * whh[h];
    float wzp  = -L2E * whh[H_ + h];
    float wnp2 = 2.f * L2E * whh[2 * H_ + h];

    const float* gp = g_gx + (size_t)b * N3_ + h;  // row t*32+b, col h
    float* op = out + idx;

    // Prime the pipeline: batch of D timesteps in registers.
    float br[D], bz[D], bn[D];
    #pragma unroll
    for (int i = 0; i < D; i++) {
        br[i] = __ldg(gp);
        bz[i] = __ldg(gp + H_);
        bn[i] = __ldg(gp + 2 * H_);
        gp += STRIDE;
    }

    for (int tb = 0; tb < T_; tb += D) {
        // Issue next batch's loads up-front (independent of the chain).
        float nr[D], nz[D], nn[D];
        if (tb + D < T_) {
            #pragma unroll
            for (int i = 0; i < D; i++) {
                nr[i] = __ldg(gp);
                nz[i] = __ldg(gp + H_);
                nn[i] = __ldg(gp + 2 * H_);
                gp += STRIDE;
            }
        }
        // Serial chain on the current batch.
        #pragma unroll
        for (int i = 0; i < D; i++) {
            float grp = br[i] * (-L2E);            // off-chain scalings
            float gzp = bz[i] * (-L2E);
            float gnp = bn[i] * (2.f * L2E);
            float er = ex2f(fmaf(wrp, hv, grp));
            float ez = ex2f(fmaf(wzp, hv, gzp));
            float r  = rcpf(1.f + er);
            float z  = rcpf(1.f + ez);
            float t0 = wnp2 * hv;                  // parallel with r chain
            float en = ex2f(fmaf(r, t0, gnp));
            float q  = rcpf(1.f + en);
            float omz = 1.f - z;
            float a   = fmaf(z, hv, omz);          // ready before q
            float bc  = -2.f * omz;
            hv = fmaf(bc, q, a);                   // (1-z)(1-2q) + z*h
            *op = hv;
            op += B_ * H_;
        }
        #pragma unroll
        for (int i = 0; i < D; i++) { br[i] = nr[i]; bz[i] = nz[i]; bn[i] = nn[i]; }
    }
    out[(size_t)T_ * B_ * H_ + idx] = hv;          // h_last
}

// ---------------- launch ----------------
extern "C" void kernel_launch(void* const* d_in, const int* in_sizes, int n_in,
                              void* d_out, int out_size) {
    const float* x   = (const float*)d_in[0];   // (T, B, I)
    const float* h0  = (const float*)d_in[1];   // (B, H)
    const float* Wih = (const float*)d_in[2];   // (3H, I)
    const float* whh = (const float*)d_in[3];   // (3, H)
    float* out = (float*)d_out;                 // (T,B,H) then (1,B,H)

    (void)in_sizes; (void)n_in; (void)out_size;

    cudaFuncSetAttribute(gemm_kernel, cudaFuncAttributeMaxDynamicSharedMemorySize, SMEM_TOTAL);

    split_x_kernel<<<(M_ * K_ / 4) / 256, 256>>>(x);
    split_w_kernel<<<(N3_ * K_ / 4) / 256, 256>>>(Wih);
    gemm_kernel<<<dim3(M_ / TM, N3_ / TN), 256, SMEM_TOTAL>>>();
    recur_kernel<<<(B_ * H_) / 128, 128>>>(h0, whh, out);
}

// round 9
// speedup vs baseline: 1.4561x; 1.1721x over previous
#include <cuda_runtime.h>
#include <cuda_fp16.h>
#include <cstdint>

// Problem dims
static constexpr int T_ = 512, B_ = 32, I_ = 512, H_ = 512;
static constexpr int M_  = T_ * B_;   // 16384 (GEMM M)
static constexpr int N3_ = 3 * H_;    // 1536  (GEMM N)
static constexpr int K_  = I_;        // 512   (GEMM K)

// GEMM tiling (mma.sync m16n8k16, baseline sm_103 features only — NO tcgen05)
static constexpr int TM = 128, TN = 128, TK = 64;
static constexpr int NCH  = K_ / TK;        // 8 K-tiles
static constexpr int NSTG = 3;
// Stage: Ah 16K | Al 16K | Bh 16K | Bl 16K  (each 128 rows x 128B swizzled)
static constexpr int STAGE = 65536;
static constexpr int SMEM_TOTAL = NSTG * STAGE;   // 196608

// ---------------- scratch (device globals; no allocation allowed) ----------------
__device__ __align__(256) __half g_xh[(size_t)M_ * K_];
__device__ __align__(256) __half g_xl[(size_t)M_ * K_];
__device__ __align__(256) __half g_wh[(size_t)N3_ * K_];
__device__ __align__(256) __half g_wl[(size_t)N3_ * K_];
__device__ __align__(256) float  g_gx[(size_t)M_ * N3_];

// ---------------- PTX helpers (all baseline sm_80+ features) ----------------
__device__ __forceinline__ uint32_t smem_u32(const void* p) {
    return (uint32_t)__cvta_generic_to_shared(p);
}
__device__ __forceinline__ void cp16(uint32_t s, const void* g) {
    asm volatile("cp.async.cg.shared.global [%0], [%1], 16;" :: "r"(s), "l"(g));
}
__device__ __forceinline__ void cp4(uint32_t s, const void* g) {
    asm volatile("cp.async.ca.shared.global [%0], [%1], 4;" :: "r"(s), "l"(g));
}
__device__ __forceinline__ void cp_commit() {
    asm volatile("cp.async.commit_group;" ::: "memory");
}
__device__ __forceinline__ void ldsm4(uint32_t& r0, uint32_t& r1, uint32_t& r2, uint32_t& r3,
                                      uint32_t a) {
    asm volatile("ldmatrix.sync.aligned.m8n8.x4.shared.b16 {%0,%1,%2,%3}, [%4];"
                 : "=r"(r0), "=r"(r1), "=r"(r2), "=r"(r3) : "r"(a));
}
__device__ __forceinline__ void mma16816(float* c, const uint32_t* a, const uint32_t* b) {
    asm volatile(
        "mma.sync.aligned.m16n8k16.row.col.f32.f16.f16.f32 "
        "{%0,%1,%2,%3}, {%4,%5,%6,%7}, {%8,%9}, {%0,%1,%2,%3};"
        : "+f"(c[0]), "+f"(c[1]), "+f"(c[2]), "+f"(c[3])
        : "r"(a[0]), "r"(a[1]), "r"(a[2]), "r"(a[3]), "r"(b[0]), "r"(b[1]));
}
__device__ __forceinline__ float ex2f(float x) {
    float y; asm("ex2.approx.f32 %0, %1;" : "=f"(y) : "f"(x)); return y;
}
__device__ __forceinline__ float rcpf(float x) {
    float y; asm("rcp.approx.f32 %0, %1;" : "=f"(y) : "f"(x)); return y;
}
__device__ __forceinline__ float lds1(uint32_t a) {
    float v; asm volatile("ld.shared.f32 %0, [%1];" : "=f"(v) : "r"(a)); return v;
}

// ---------------- prep: split fp32 -> fp16 hi + lo ----------------
__device__ __forceinline__ void split1(float v, __half& h, __half& l) {
    h = __float2half_rn(v);
    l = __float2half_rn(v - __half2float(h));
}

__global__ void split_x_kernel(const float* __restrict__ src) {
    int i = blockIdx.x * blockDim.x + threadIdx.x;          // one float4 per thread
    float4 v = ((const float4*)src)[i];
    __half h0, h1, h2, h3, l0, l1, l2, l3;
    split1(v.x, h0, l0); split1(v.y, h1, l1); split1(v.z, h2, l2); split1(v.w, h3, l3);
    __half2* ph = (__half2*)g_xh;
    __half2* pl = (__half2*)g_xl;
    ph[2 * i]     = __halves2half2(h0, h1);
    ph[2 * i + 1] = __halves2half2(h2, h3);
    pl[2 * i]     = __halves2half2(l0, l1);
    pl[2 * i + 1] = __halves2half2(l2, l3);
}

__global__ void split_w_kernel(const float* __restrict__ src) {
    int i = blockIdx.x * blockDim.x + threadIdx.x;
    float4 v = ((const float4*)src)[i];
    __half h0, h1, h2, h3, l0, l1, l2, l3;
    split1(v.x, h0, l0); split1(v.y, h1, l1); split1(v.z, h2, l2); split1(v.w, h3, l3);
    __half2* ph = (__half2*)g_wh;
    __half2* pl = (__half2*)g_wl;
    ph[2 * i]     = __halves2half2(h0, h1);
    ph[2 * i + 1] = __halves2half2(h2, h3);
    pl[2 * i]     = __halves2half2(l0, l1);
    pl[2 * i + 1] = __halves2half2(l2, l3);
}

// ---------------- GEMM: gx = Xsplit @ Wsplit^T via mma.sync (3-product fp16) ------
// Smem row layout: 64 fp16 = 128B per row; 16B chunk j stored at (j ^ (row&7))*16.
__device__ __forceinline__ void load_quarter(uint32_t dst, const __half* __restrict__ g,
                                             int row0, int k0, int tid) {
    // 128 rows x 8 chunks of 16B = 1024 cp16, 256 threads -> 4 each
    #pragma unroll
    for (int u = 0; u < 4; u++) {
        int i = tid + u * 256;
        int r = i >> 3, j = i & 7;
        cp16(dst + (uint32_t)(r * 128 + ((j ^ (r & 7)) << 4)),
             g + (size_t)(row0 + r) * K_ + k0 + j * 8);
    }
}

__device__ __forceinline__ void load_stage(uint32_t st, int m0, int n0, int k0, int tid) {
    load_quarter(st,          g_xh, m0, k0, tid);
    load_quarter(st + 16384u, g_xl, m0, k0, tid);
    load_quarter(st + 32768u, g_wh, n0, k0, tid);
    load_quarter(st + 49152u, g_wl, n0, k0, tid);
    cp_commit();
}

__global__ __launch_bounds__(256, 1) void gemm_kernel() {
    extern __shared__ __align__(1024) char smem[];
    uint32_t sb = smem_u32(smem);
    int tid = threadIdx.x, lane = tid & 31, wid = tid >> 5;
    int wm = wid & 1, wn = wid >> 1;          // 2 x 4 warp grid; warp tile 64m x 32n
    int m0 = blockIdx.x * TM, n0 = blockIdx.y * TN;
    int g = lane >> 3;                         // ldmatrix lane group

    float acc[4][4][4];
    #pragma unroll
    for (int a = 0; a < 4; a++)
        #pragma unroll
        for (int b = 0; b < 4; b++)
            #pragma unroll
            for (int c = 0; c < 4; c++) acc[a][b][c] = 0.f;

    load_stage(sb,         m0, n0, 0,  tid);
    load_stage(sb + STAGE, m0, n0, TK, tid);

    for (int cc = 0; cc < NCH; cc++) {
        if (cc < NCH - 1) asm volatile("cp.async.wait_group 1;" ::: "memory");
        else              asm volatile("cp.async.wait_group 0;" ::: "memory");
        __syncthreads();

        uint32_t st = sb + (uint32_t)(cc % 3) * STAGE;
        #pragma unroll
        for (int ks = 0; ks < 4; ks++) {
            // A fragments (hi, lo): 4 m-frags of 16 rows each
            uint32_t ah[4][4], al[4][4];
            #pragma unroll
            for (int mi = 0; mi < 4; mi++) {
                int row = wm * 64 + mi * 16 + ((g & 1) << 3) + (lane & 7);
                uint32_t off = (uint32_t)(row * 128 +
                                (((ks * 2 + (g >> 1)) ^ (row & 7)) << 4));
                ldsm4(ah[mi][0], ah[mi][1], ah[mi][2], ah[mi][3], st + off);
                ldsm4(al[mi][0], al[mi][1], al[mi][2], al[mi][3], st + 16384u + off);
            }
            // B fragments (hi, lo): 4 n-frags of 8, loaded in pairs via x4
            uint32_t bh[4][2], bl[4][2];
            #pragma unroll
            for (int p = 0; p < 2; p++) {
                int row = wn * 32 + p * 16 + ((g >> 1) << 3) + (lane & 7);
                uint32_t off = (uint32_t)(row * 128 +
                                (((ks * 2 + (g & 1)) ^ (row & 7)) << 4));
                uint32_t r0, r1, r2, r3;
                ldsm4(r0, r1, r2, r3, st + 32768u + off);
                bh[2 * p][0] = r0; bh[2 * p][1] = r1;
                bh[2 * p + 1][0] = r2; bh[2 * p + 1][1] = r3;
                ldsm4(r0, r1, r2, r3, st + 49152u + off);
                bl[2 * p][0] = r0; bl[2 * p][1] = r1;
                bl[2 * p + 1][0] = r2; bl[2 * p + 1][1] = r3;
            }
            // 3-product split: ah*bh + ah*bl + al*bh  (lo*lo dropped, ~2^-22)
            #pragma unroll
            for (int mi = 0; mi < 4; mi++)
                #pragma unroll
                for (int ni = 0; ni < 4; ni++) {
                    mma16816(acc[mi][ni], ah[mi], bh[ni]);
                    mma16816(acc[mi][ni], ah[mi], bl[ni]);
                    mma16816(acc[mi][ni], al[mi], bh[ni]);
                }
        }
        __syncthreads();
        if (cc + 2 < NCH)
            load_stage(sb + (uint32_t)((cc + 2) % 3) * STAGE, m0, n0, (cc + 2) * TK, tid);
    }

    // Epilogue: direct float2 stores to g_gx
    #pragma unroll
    for (int mi = 0; mi < 4; mi++) {
        int row = m0 + wm * 64 + mi * 16 + (lane >> 2);
        #pragma unroll
        for (int ni = 0; ni < 4; ni++) {
            int col = n0 + wn * 32 + ni * 8 + 2 * (lane & 3);
            *(float2*)(g_gx + (size_t)row * N3_ + col) =
                make_float2(acc[mi][ni][0], acc[mi][ni][1]);
            *(float2*)(g_gx + (size_t)(row + 8) * N3_ + col) =
                make_float2(acc[mi][ni][2], acc[mi][ni][3]);
        }
    }
}

// ---------------- IndGRU recurrence ----------------
// One thread per (b, h) channel. Deep prefetch pipeline lives in SMEM via
// per-thread cp.async (4B) — zero register cost, so ptxas cannot collapse it
// (the R7 register double-buffer was defeated by register pressure: regs=54).
//   16-slot ring, DEPTH=15 timesteps in flight; group g <=> timestep g, so
//   wait_group 13 at iter t guarantees timestep t+1 resident. Next-step gates
//   are LDS'd before computing step t, keeping LDS off the serial chain.
// Math (validated at rel_err 1.7e-6):
//   r = rcp(1 + ex2(wr'*h + gr'))            wr' = -log2e*wr
//   q = rcp(1 + ex2(gn' + r*(wn'*h)))        wn' = 2log2e*wn
//   h' = fma(-2(1-z), q, fma(z, h, 1-z))
__global__ __launch_bounds__(128) void recur_kernel(const float* __restrict__ h0,
                                                    const float* __restrict__ whh,
                                                    float* __restrict__ out) {
    constexpr float L2E   = 1.4426950408889634f;
    constexpr int   SLOTS = 16, DEPTH = 15;
    constexpr int   STRIDE = B_ * N3_;             // floats per timestep in g_gx

    __shared__ float buf[SLOTS * 3 * 128];         // slot stride 1536B, gate stride 512B

    int tid = threadIdx.x;
    int idx = blockIdx.x * 128 + tid;              // 0..16383 = b*512 + h
    int h = idx & (H_ - 1);
    int b = idx >> 9;

    float hv   = h0[idx];
    float wrp  = -L2E * whh[h];
    float wzp  = -L2E * whh[H_ + h];
    float wnp2 = 2.f * L2E * whh[2 * H_ + h];

    const float* gp = g_gx + (size_t)b * N3_ + h;  // row t*32+b, col h
    float* op = out + idx;

    uint32_t sbase = smem_u32(buf) + (uint32_t)tid * 4u;

    // Prime: timesteps 0..DEPTH-1, one commit group per timestep.
    #pragma unroll
    for (int s = 0; s < DEPTH; s++) {
        uint32_t sa = sbase + (uint32_t)s * 1536u;
        cp4(sa,         gp);
        cp4(sa + 512u,  gp + H_);
        cp4(sa + 1024u, gp + 2 * H_);
        cp_commit();
        gp += STRIDE;
    }

    // Load timestep 0 into cur regs (group 0 done when pending <= DEPTH-1).
    asm volatile("cp.async.wait_group 14;" ::: "memory");
    float cr = lds1(sbase), cz = lds1(sbase + 512u), cn = lds1(sbase + 1024u);

    for (int t = 0; t < T_; t++) {
        // Guarantee timestep t+1 resident: completed groups >= t+2.
        asm volatile("cp.async.wait_group 13;" ::: "memory");
        int tn = (t + 1 < T_) ? t + 1 : t;
        uint32_t na = sbase + (uint32_t)((tn & (SLOTS - 1)) * 1536);
        float nr = lds1(na), nz = lds1(na + 512u), nn = lds1(na + 1024u);

        // Serial chain on timestep t.
        float grp = cr * (-L2E);
        float gzp = cz * (-L2E);
        float gnp = cn * (2.f * L2E);
        float er = ex2f(fmaf(wrp, hv, grp));
        float ez = ex2f(fmaf(wzp, hv, gzp));
        float r  = rcpf(1.f + er);
        float z  = rcpf(1.f + ez);
        float t0 = wnp2 * hv;
        float en = ex2f(fmaf(r, t0, gnp));
        float q  = rcpf(1.f + en);
        float omz = 1.f - z;
        float a   = fmaf(z, hv, omz);
        float bc  = -2.f * omz;
        hv = fmaf(bc, q, a);                       // (1-z)(1-2q) + z*h
        *op = hv;
        op += B_ * H_;

        // Refill: timestep t+DEPTH into slot (t+DEPTH)%16 = (t-1)%16 (consumed).
        if (t + DEPTH < T_) {
            uint32_t wa = sbase + (uint32_t)(((t + DEPTH) & (SLOTS - 1)) * 1536);
            cp4(wa,         gp);
            cp4(wa + 512u,  gp + H_);
            cp4(wa + 1024u, gp + 2 * H_);
            gp += STRIDE;
        }
        cp_commit();                               // always commit: group g == timestep g
        cr = nr; cz = nz; cn = nn;
    }
    out[(size_t)T_ * B_ * H_ + idx] = hv;          // h_last
}

// ---------------- launch ----------------
extern "C" void kernel_launch(void* const* d_in, const int* in_sizes, int n_in,
                              void* d_out, int out_size) {
    const float* x   = (const float*)d_in[0];   // (T, B, I)
    const float* h0  = (const float*)d_in[1];   // (B, H)
    const float* Wih = (const float*)d_in[2];   // (3H, I)
    const float* whh = (const float*)d_in[3];   // (3, H)
    float* out = (float*)d_out;                 // (T,B,H) then (1,B,H)

    (void)in_sizes; (void)n_in; (void)out_size;

    cudaFuncSetAttribute(gemm_kernel, cudaFuncAttributeMaxDynamicSharedMemorySize, SMEM_TOTAL);

    split_x_kernel<<<(M_ * K_ / 4) / 256, 256>>>(x);
    split_w_kernel<<<(N3_ * K_ / 4) / 256, 256>>>(Wih);
    gemm_kernel<<<dim3(M_ / TM, N3_ / TN), 256, SMEM_TOTAL>>>();
    recur_kernel<<<(B_ * H_) / 128, 128>>>(h0, whh, out);
}

// round 11
// speedup vs baseline: 1.6490x; 1.1325x over previous
#include <cuda_runtime.h>
#include <cuda_fp16.h>
#include <cstdint>

// Problem dims
static constexpr int T_ = 512, B_ = 32, I_ = 512, H_ = 512;
static constexpr int M_  = T_ * B_;   // 16384 (GEMM M)
static constexpr int N3_ = 3 * H_;    // 1536  (GEMM N)
static constexpr int K_  = I_;        // 512   (GEMM K)

// GEMM tiling (mma.sync m16n8k16, baseline sm_103 features only — NO tcgen05)
static constexpr int TM = 128, TN = 128, TK = 64;
static constexpr int NCH  = K_ / TK;        // 8 K-tiles
static constexpr int NSTG = 4;
// Stage: Ah 16K | Bh 16K | Bl 16K  (each 128 rows x 128B swizzled)
static constexpr int STAGE = 49152;
static constexpr int SMEM_TOTAL = NSTG * STAGE;   // 196608

// ---------------- scratch (device globals; no allocation allowed) ----------------
__device__ __align__(256) __half g_xh[(size_t)M_ * K_];
__device__ __align__(256) __half g_wh[(size_t)N3_ * K_];
__device__ __align__(256) __half g_wl[(size_t)N3_ * K_];
__device__ __align__(256) float  g_gx[(size_t)M_ * N3_];

// ---------------- PTX helpers (all baseline sm_80+ features) ----------------
__device__ __forceinline__ uint32_t smem_u32(const void* p) {
    return (uint32_t)__cvta_generic_to_shared(p);
}
__device__ __forceinline__ void cp16(uint32_t s, const void* g) {
    asm volatile("cp.async.cg.shared.global [%0], [%1], 16;" :: "r"(s), "l"(g));
}
__device__ __forceinline__ void cp4(uint32_t s, const void* g) {
    asm volatile("cp.async.ca.shared.global [%0], [%1], 4;" :: "r"(s), "l"(g));
}
__device__ __forceinline__ void cp_commit() {
    asm volatile("cp.async.commit_group;" ::: "memory");
}
__device__ __forceinline__ void ldsm4(uint32_t& r0, uint32_t& r1, uint32_t& r2, uint32_t& r3,
                                      uint32_t a) {
    asm volatile("ldmatrix.sync.aligned.m8n8.x4.shared.b16 {%0,%1,%2,%3}, [%4];"
                 : "=r"(r0), "=r"(r1), "=r"(r2), "=r"(r3) : "r"(a));
}
__device__ __forceinline__ void mma16816(float* c, const uint32_t* a, const uint32_t* b) {
    asm volatile(
        "mma.sync.aligned.m16n8k16.row.col.f32.f16.f16.f32 "
        "{%0,%1,%2,%3}, {%4,%5,%6,%7}, {%8,%9}, {%0,%1,%2,%3};"
        : "+f"(c[0]), "+f"(c[1]), "+f"(c[2]), "+f"(c[3])
        : "r"(a[0]), "r"(a[1]), "r"(a[2]), "r"(a[3]), "r"(b[0]), "r"(b[1]));
}
__device__ __forceinline__ float ex2f(float x) {
    float y; asm("ex2.approx.f32 %0, %1;" : "=f"(y) : "f"(x)); return y;
}
__device__ __forceinline__ float rcpf(float x) {
    float y; asm("rcp.approx.f32 %0, %1;" : "=f"(y) : "f"(x)); return y;
}
__device__ __forceinline__ float lds1(uint32_t a) {
    float v; asm volatile("ld.shared.f32 %0, [%1];" : "=f"(v) : "r"(a)); return v;
}

// ---------------- prep ----------------
__device__ __forceinline__ void split1(float v, __half& h, __half& l) {
    h = __float2half_rn(v);
    l = __float2half_rn(v - __half2float(h));
}

// x: hi only (2-product split drops x_lo; its contribution is ~2^-11 relative)
__global__ void split_x_kernel(const float* __restrict__ src) {
    int i = blockIdx.x * blockDim.x + threadIdx.x;          // one float4 per thread
    float4 v = ((const float4*)src)[i];
    __half2* ph = (__half2*)g_xh;
    ph[2 * i]     = __halves2half2(__float2half_rn(v.x), __float2half_rn(v.y));
    ph[2 * i + 1] = __halves2half2(__float2half_rn(v.z), __float2half_rn(v.w));
}

__global__ void split_w_kernel(const float* __restrict__ src) {
    int i = blockIdx.x * blockDim.x + threadIdx.x;
    float4 v = ((const float4*)src)[i];
    __half h0, h1, h2, h3, l0, l1, l2, l3;
    split1(v.x, h0, l0); split1(v.y, h1, l1); split1(v.z, h2, l2); split1(v.w, h3, l3);
    __half2* ph = (__half2*)g_wh;
    __half2* pl = (__half2*)g_wl;
    ph[2 * i]     = __halves2half2(h0, h1);
    ph[2 * i + 1] = __halves2half2(h2, h3);
    pl[2 * i]     = __halves2half2(l0, l1);
    pl[2 * i + 1] = __halves2half2(l2, l3);
}

// ---------------- GEMM: gx = xh @ (wh + wl)^T via mma.sync (2-product) -----------
// Smem row layout: 64 fp16 = 128B per row; 16B chunk j stored at (j ^ (row&7))*16.
__device__ __forceinline__ void load_quarter(uint32_t dst, const __half* __restrict__ g,
                                             int row0, int k0, int tid) {
    // 128 rows x 8 chunks of 16B = 1024 cp16, 256 threads -> 4 each
    #pragma unroll
    for (int u = 0; u < 4; u++) {
        int i = tid + u * 256;
        int r = i >> 3, j = i & 7;
        cp16(dst + (uint32_t)(r * 128 + ((j ^ (r & 7)) << 4)),
             g + (size_t)(row0 + r) * K_ + k0 + j * 8);
    }
}

__device__ __forceinline__ void load_stage(uint32_t st, int m0, int n0, int k0, int tid) {
    load_quarter(st,          g_xh, m0, k0, tid);
    load_quarter(st + 16384u, g_wh, n0, k0, tid);
    load_quarter(st + 32768u, g_wl, n0, k0, tid);
    cp_commit();
}

__global__ __launch_bounds__(256, 1) void gemm_kernel() {
    extern __shared__ __align__(1024) char smem[];
    uint32_t sb = smem_u32(smem);
    int tid = threadIdx.x, lane = tid & 31, wid = tid >> 5;
    int wm = wid & 1, wn = wid >> 1;          // 2 x 4 warp grid; warp tile 64m x 32n
    int m0 = blockIdx.x * TM, n0 = blockIdx.y * TN;
    int g = lane >> 3;                         // ldmatrix lane group

    float acc[4][4][4];
    #pragma unroll
    for (int a = 0; a < 4; a++)
        #pragma unroll
        for (int b = 0; b < 4; b++)
            #pragma unroll
            for (int c = 0; c < 4; c++) acc[a][b][c] = 0.f;

    load_stage(sb,             m0, n0, 0,      tid);
    load_stage(sb + STAGE,     m0, n0, TK,     tid);
    load_stage(sb + 2 * STAGE, m0, n0, 2 * TK, tid);

    for (int cc = 0; cc < NCH; cc++) {
        if (cc < 6)       asm volatile("cp.async.wait_group 2;" ::: "memory");
        else if (cc == 6) asm volatile("cp.async.wait_group 1;" ::: "memory");
        else              asm volatile("cp.async.wait_group 0;" ::: "memory");
        __syncthreads();

        uint32_t st = sb + (uint32_t)(cc % NSTG) * STAGE;
        #pragma unroll
        for (int ks = 0; ks < 4; ks++) {
            // A fragments (hi only): 4 m-frags of 16 rows each
            uint32_t ah[4][4];
            #pragma unroll
            for (int mi = 0; mi < 4; mi++) {
                int row = wm * 64 + mi * 16 + ((g & 1) << 3) + (lane & 7);
                uint32_t off = (uint32_t)(row * 128 +
                                (((ks * 2 + (g >> 1)) ^ (row & 7)) << 4));
                ldsm4(ah[mi][0], ah[mi][1], ah[mi][2], ah[mi][3], st + off);
            }
            // B fragments (hi, lo): 4 n-frags of 8, loaded in pairs via x4
            uint32_t bh[4][2], bl[4][2];
            #pragma unroll
            for (int p = 0; p < 2; p++) {
                int row = wn * 32 + p * 16 + ((g >> 1) << 3) + (lane & 7);
                uint32_t off = (uint32_t)(row * 128 +
                                (((ks * 2 + (g & 1)) ^ (row & 7)) << 4));
                uint32_t r0, r1, r2, r3;
                ldsm4(r0, r1, r2, r3, st + 16384u + off);
                bh[2 * p][0] = r0; bh[2 * p][1] = r1;
                bh[2 * p + 1][0] = r2; bh[2 * p + 1][1] = r3;
                ldsm4(r0, r1, r2, r3, st + 32768u + off);
                bl[2 * p][0] = r0; bl[2 * p][1] = r1;
                bl[2 * p + 1][0] = r2; bl[2 * p + 1][1] = r3;
            }
            // 2-product split: ah*bh + ah*bl = ah*(bh+bl); dropped xl*W ~ 2^-11
            #pragma unroll
            for (int mi = 0; mi < 4; mi++)
                #pragma unroll
                for (int ni = 0; ni < 4; ni++) {
                    mma16816(acc[mi][ni], ah[mi], bh[ni]);
                    mma16816(acc[mi][ni], ah[mi], bl[ni]);
                }
        }
        __syncthreads();
        if (cc + 3 < NCH)
            load_stage(sb + (uint32_t)((cc + 3) % NSTG) * STAGE, m0, n0, (cc + 3) * TK, tid);
    }

    // Epilogue: direct float2 stores to g_gx
    #pragma unroll
    for (int mi = 0; mi < 4; mi++) {
        int row = m0 + wm * 64 + mi * 16 + (lane >> 2);
        #pragma unroll
        for (int ni = 0; ni < 4; ni++) {
            int col = n0 + wn * 32 + ni * 8 + 2 * (lane & 3);
            *(float2*)(g_gx + (size_t)row * N3_ + col) =
                make_float2(acc[mi][ni][0], acc[mi][ni][1]);
            *(float2*)(g_gx + (size_t)(row + 8) * N3_ + col) =
                make_float2(acc[mi][ni][2], acc[mi][ni][3]);
        }
    }
}

// ---------------- IndGRU recurrence ----------------
// TWO independent channels per thread (ILP=2) to hide the serial-chain latency:
// thread handles (b, h) and (b+16, h) — same h, so gate weights are shared.
// Deep prefetch pipeline in SMEM via per-thread cp.async (16-slot ring,
// DEPTH=15 timesteps, group g == timestep g; wait_group 13 at iter t makes
// timestep t+1 resident, LDS'd off the critical chain).
// Math (validated at rel_err 1.7e-6):
//   r = rcp(1 + ex2(wr'*h + gr'))            wr' = -log2e*wr
//   q = rcp(1 + ex2(gn' + r*(wn'*h)))        wn' = 2log2e*wn
//   h' = fma(-2(1-z), q, fma(z, h, 1-z))
__global__ __launch_bounds__(64) void recur_kernel(const float* __restrict__ h0,
                                                   const float* __restrict__ whh,
                                                   float* __restrict__ out) {
    constexpr float L2E   = 1.4426950408889634f;
    constexpr int   SLOTS = 16, DEPTH = 15;
    constexpr int   STRIDE = B_ * N3_;             // floats per timestep in g_gx

    __shared__ float buf[SLOTS * 6 * 64];          // slot 1536B; 6 gates x 256B

    int tid  = threadIdx.x;
    int idx0 = blockIdx.x * 64 + tid;              // 0..8191: b = 0..15
    int h = idx0 & (H_ - 1);
    int b = idx0 >> 9;
    int idx1 = idx0 + 8192;                        // b+16, same h

    float hv0 = h0[idx0], hv1 = h0[idx1];
    float wrp  = -L2E * whh[h];
    float wzp  = -L2E * whh[H_ + h];
    float wnp2 = 2.f * L2E * whh[2 * H_ + h];

    const float* gp0 = g_gx + (size_t)b * N3_ + h;
    const float* gp1 = gp0 + (size_t)16 * N3_;
    float* op0 = out + idx0;
    float* op1 = out + idx1;

    uint32_t sbase = smem_u32(buf) + (uint32_t)tid * 4u;

    // Prime: timesteps 0..DEPTH-1, one commit group per timestep (6 cp4 each).
    #pragma unroll
    for (int s = 0; s < DEPTH; s++) {
        uint32_t sa = sbase + (uint32_t)s * 1536u;
        cp4(sa,          gp0);
        cp4(sa + 256u,   gp0 + H_);
        cp4(sa + 512u,   gp0 + 2 * H_);
        cp4(sa + 768u,   gp1);
        cp4(sa + 1024u,  gp1 + H_);
        cp4(sa + 1280u,  gp1 + 2 * H_);
        cp_commit();
        gp0 += STRIDE; gp1 += STRIDE;
    }

    asm volatile("cp.async.wait_group 14;" ::: "memory");
    float cr0 = lds1(sbase),          cz0 = lds1(sbase + 256u),  cn0 = lds1(sbase + 512u);
    float cr1 = lds1(sbase + 768u),   cz1 = lds1(sbase + 1024u), cn1 = lds1(sbase + 1280u);

    for (int t = 0; t < T_; t++) {
        asm volatile("cp.async.wait_group 13;" ::: "memory");
        int tn = (t + 1 < T_) ? t + 1 : t;
        uint32_t na = sbase + (uint32_t)((tn & (SLOTS - 1)) * 1536);
        float nr0 = lds1(na),          nz0 = lds1(na + 256u),  nn0 = lds1(na + 512u);
        float nr1 = lds1(na + 768u),   nz1 = lds1(na + 1024u), nn1 = lds1(na + 1280u);

        // Two interleaved serial chains (independent -> latency hidden).
        float er0 = ex2f(fmaf(wrp, hv0, cr0 * (-L2E)));
        float er1 = ex2f(fmaf(wrp, hv1, cr1 * (-L2E)));
        float ez0 = ex2f(fmaf(wzp, hv0, cz0 * (-L2E)));
        float ez1 = ex2f(fmaf(wzp, hv1, cz1 * (-L2E)));
        float r0  = rcpf(1.f + er0);
        float r1  = rcpf(1.f + er1);
        float z0  = rcpf(1.f + ez0);
        float z1  = rcpf(1.f + ez1);
        float en0 = ex2f(fmaf(r0, wnp2 * hv0, cn0 * (2.f * L2E)));
        float en1 = ex2f(fmaf(r1, wnp2 * hv1, cn1 * (2.f * L2E)));
        float q0  = rcpf(1.f + en0);
        float q1  = rcpf(1.f + en1);
        float omz0 = 1.f - z0, omz1 = 1.f - z1;
        hv0 = fmaf(-2.f * omz0, q0, fmaf(z0, hv0, omz0));
        hv1 = fmaf(-2.f * omz1, q1, fmaf(z1, hv1, omz1));
        *op0 = hv0; op0 += B_ * H_;
        *op1 = hv1; op1 += B_ * H_;

        // Refill slot (t+DEPTH)%16 = (t-1)%16 (already consumed).
        if (t + DEPTH < T_) {
            uint32_t wa = sbase + (uint32_t)(((t + DEPTH) & (SLOTS - 1)) * 1536);
            cp4(wa,          gp0);
            cp4(wa + 256u,   gp0 + H_);
            cp4(wa + 512u,   gp0 + 2 * H_);
            cp4(wa + 768u,   gp1);
            cp4(wa + 1024u,  gp1 + H_);
            cp4(wa + 1280u,  gp1 + 2 * H_);
            gp0 += STRIDE; gp1 += STRIDE;
        }
        cp_commit();                               // group g == timestep g, always
        cr0 = nr0; cz0 = nz0; cn0 = nn0;
        cr1 = nr1; cz1 = nz1; cn1 = nn1;
    }
    out[(size_t)T_ * B_ * H_ + idx0] = hv0;        // h_last
    out[(size_t)T_ * B_ * H_ + idx1] = hv1;
}

// ---------------- launch ----------------
extern "C" void kernel_launch(void* const* d_in, const int* in_sizes, int n_in,
                              void* d_out, int out_size) {
    const float* x   = (const float*)d_in[0];   // (T, B, I)
    const float* h0  = (const float*)d_in[1];   // (B, H)
    const float* Wih = (const float*)d_in[2];   // (3H, I)
    const float* whh = (const float*)d_in[3];   // (3, H)
    float* out = (float*)d_out;                 // (T,B,H) then (1,B,H)

    (void)in_sizes; (void)n_in; (void)out_size;

    cudaFuncSetAttribute(gemm_kernel, cudaFuncAttributeMaxDynamicSharedMemorySize, SMEM_TOTAL);

    split_x_kernel<<<(M_ * K_ / 4) / 256, 256>>>(x);
    split_w_kernel<<<(N3_ * K_ / 4) / 256, 256>>>(Wih);
    gemm_kernel<<<dim3(M_ / TM, N3_ / TN), 256, SMEM_TOTAL>>>();
    recur_kernel<<<128, 64>>>(h0, whh, out);
}

// round 12
// speedup vs baseline: 1.7657x; 1.0708x over previous
#include <cuda_runtime.h>
#include <cuda_fp16.h>
#include <cstdint>

// Problem dims
static constexpr int T_ = 512, B_ = 32, I_ = 512, H_ = 512;
static constexpr int M_  = T_ * B_;   // 16384 (GEMM M)
static constexpr int N3_ = 3 * H_;    // 1536  (GEMM N)
static constexpr int K_  = I_;        // 512   (GEMM K)

// GEMM tiling (mma.sync m16n8k16, baseline sm_103 features only — NO tcgen05)
static constexpr int TM = 128, TN = 128, TK = 64;
static constexpr int NCH  = K_ / TK;        // 8 K-tiles
static constexpr int NSTG = 4;
// Stage: Ah 16K | Bh 16K | Bl 16K  (each 128 rows x 128B swizzled)
static constexpr int STAGE = 49152;
static constexpr int SMEM_TOTAL = NSTG * STAGE;   // 196608

// ---------------- scratch (device globals; no allocation allowed) ----------------
__device__ __align__(256) __half g_xh[(size_t)M_ * K_];
__device__ __align__(256) __half g_wh[(size_t)N3_ * K_];
__device__ __align__(256) __half g_wl[(size_t)N3_ * K_];
__device__ __align__(256) float  g_gx[(size_t)M_ * N3_];

// ---------------- PTX helpers (all baseline sm_80+ features) ----------------
__device__ __forceinline__ uint32_t smem_u32(const void* p) {
    return (uint32_t)__cvta_generic_to_shared(p);
}
__device__ __forceinline__ void cp16(uint32_t s, const void* g) {
    asm volatile("cp.async.cg.shared.global [%0], [%1], 16;" :: "r"(s), "l"(g));
}
__device__ __forceinline__ void cp4(uint32_t s, const void* g) {
    asm volatile("cp.async.ca.shared.global [%0], [%1], 4;" :: "r"(s), "l"(g));
}
__device__ __forceinline__ void cp_commit() {
    asm volatile("cp.async.commit_group;" ::: "memory");
}
__device__ __forceinline__ void ldsm4(uint32_t& r0, uint32_t& r1, uint32_t& r2, uint32_t& r3,
                                      uint32_t a) {
    asm volatile("ldmatrix.sync.aligned.m8n8.x4.shared.b16 {%0,%1,%2,%3}, [%4];"
                 : "=r"(r0), "=r"(r1), "=r"(r2), "=r"(r3) : "r"(a));
}
__device__ __forceinline__ void mma16816(float* c, const uint32_t* a, const uint32_t* b) {
    asm volatile(
        "mma.sync.aligned.m16n8k16.row.col.f32.f16.f16.f32 "
        "{%0,%1,%2,%3}, {%4,%5,%6,%7}, {%8,%9}, {%0,%1,%2,%3};"
        : "+f"(c[0]), "+f"(c[1]), "+f"(c[2]), "+f"(c[3])
        : "r"(a[0]), "r"(a[1]), "r"(a[2]), "r"(a[3]), "r"(b[0]), "r"(b[1]));
}
__device__ __forceinline__ float ex2f(float x) {
    float y; asm("ex2.approx.f32 %0, %1;" : "=f"(y) : "f"(x)); return y;
}
__device__ __forceinline__ float rcpf(float x) {
    float y; asm("rcp.approx.f32 %0, %1;" : "=f"(y) : "f"(x)); return y;
}
__device__ __forceinline__ float lds1(uint32_t a) {
    float v; asm volatile("ld.shared.f32 %0, [%1];" : "=f"(v) : "r"(a)); return v;
}

// ---------------- prep ----------------
static constexpr float L2E_ = 1.4426950408889634f;

__device__ __forceinline__ void split1(float v, __half& h, __half& l) {
    h = __float2half_rn(v);
    l = __float2half_rn(v - __half2float(h));
}

// x: hi only (2-product split drops x_lo; its contribution is ~2^-11 relative)
__global__ void split_x_kernel(const float* __restrict__ src) {
    int i = blockIdx.x * blockDim.x + threadIdx.x;          // one float4 per thread
    float4 v = ((const float4*)src)[i];
    __half2* ph = (__half2*)g_xh;
    ph[2 * i]     = __halves2half2(__float2half_rn(v.x), __float2half_rn(v.y));
    ph[2 * i + 1] = __halves2half2(__float2half_rn(v.z), __float2half_rn(v.w));
}

// W rows pre-scaled per gate so gx arrives activation-ready:
//   r,z rows * (-log2e);  n rows * (+2 log2e)
__global__ void split_w_kernel(const float* __restrict__ src) {
    int i = blockIdx.x * blockDim.x + threadIdx.x;
    int row = i >> 7;                                       // (i*4)/K_
    float sc = (row >= 2 * H_) ? (2.f * L2E_) : (-L2E_);
    float4 v = ((const float4*)src)[i];
    v.x *= sc; v.y *= sc; v.z *= sc; v.w *= sc;
    __half h0, h1, h2, h3, l0, l1, l2, l3;
    split1(v.x, h0, l0); split1(v.y, h1, l1); split1(v.z, h2, l2); split1(v.w, h3, l3);
    __half2* ph = (__half2*)g_wh;
    __half2* pl = (__half2*)g_wl;
    ph[2 * i]     = __halves2half2(h0, h1);
    ph[2 * i + 1] = __halves2half2(h2, h3);
    pl[2 * i]     = __halves2half2(l0, l1);
    pl[2 * i + 1] = __halves2half2(l2, l3);
}

// ---------------- GEMM: gx = xh @ (wh + wl)^T via mma.sync (2-product) -----------
// Smem row layout: 64 fp16 = 128B per row; 16B chunk j stored at (j ^ (row&7))*16.
__device__ __forceinline__ void load_quarter(uint32_t dst, const __half* __restrict__ g,
                                             int row0, int k0, int tid) {
    // 128 rows x 8 chunks of 16B = 1024 cp16, 256 threads -> 4 each
    #pragma unroll
    for (int u = 0; u < 4; u++) {
        int i = tid + u * 256;
        int r = i >> 3, j = i & 7;
        cp16(dst + (uint32_t)(r * 128 + ((j ^ (r & 7)) << 4)),
             g + (size_t)(row0 + r) * K_ + k0 + j * 8);
    }
}

__device__ __forceinline__ void load_stage(uint32_t st, int m0, int n0, int k0, int tid) {
    load_quarter(st,          g_xh, m0, k0, tid);
    load_quarter(st + 16384u, g_wh, n0, k0, tid);
    load_quarter(st + 32768u, g_wl, n0, k0, tid);
    cp_commit();
}

__global__ __launch_bounds__(256, 1) void gemm_kernel() {
    extern __shared__ __align__(1024) char smem[];
    uint32_t sb = smem_u32(smem);
    int tid = threadIdx.x, lane = tid & 31, wid = tid >> 5;
    int wm = wid & 1, wn = wid >> 1;          // 2 x 4 warp grid; warp tile 64m x 32n
    int m0 = blockIdx.x * TM, n0 = blockIdx.y * TN;
    int g = lane >> 3;                         // ldmatrix lane group

    float acc[4][4][4];
    #pragma unroll
    for (int a = 0; a < 4; a++)
        #pragma unroll
        for (int b = 0; b < 4; b++)
            #pragma unroll
            for (int c = 0; c < 4; c++) acc[a][b][c] = 0.f;

    load_stage(sb,             m0, n0, 0,      tid);
    load_stage(sb + STAGE,     m0, n0, TK,     tid);
    load_stage(sb + 2 * STAGE, m0, n0, 2 * TK, tid);

    for (int cc = 0; cc < NCH; cc++) {
        if (cc < 6)       asm volatile("cp.async.wait_group 2;" ::: "memory");
        else if (cc == 6) asm volatile("cp.async.wait_group 1;" ::: "memory");
        else              asm volatile("cp.async.wait_group 0;" ::: "memory");
        __syncthreads();

        uint32_t st = sb + (uint32_t)(cc % NSTG) * STAGE;
        #pragma unroll
        for (int ks = 0; ks < 4; ks++) {
            // A fragments (hi only): 4 m-frags of 16 rows each
            uint32_t ah[4][4];
            #pragma unroll
            for (int mi = 0; mi < 4; mi++) {
                int row = wm * 64 + mi * 16 + ((g & 1) << 3) + (lane & 7);
                uint32_t off = (uint32_t)(row * 128 +
                                (((ks * 2 + (g >> 1)) ^ (row & 7)) << 4));
                ldsm4(ah[mi][0], ah[mi][1], ah[mi][2], ah[mi][3], st + off);
            }
            // B fragments (hi, lo): 4 n-frags of 8, loaded in pairs via x4
            uint32_t bh[4][2], bl[4][2];
            #pragma unroll
            for (int p = 0; p < 2; p++) {
                int row = wn * 32 + p * 16 + ((g >> 1) << 3) + (lane & 7);
                uint32_t off = (uint32_t)(row * 128 +
                                (((ks * 2 + (g & 1)) ^ (row & 7)) << 4));
                uint32_t r0, r1, r2, r3;
                ldsm4(r0, r1, r2, r3, st + 16384u + off);
                bh[2 * p][0] = r0; bh[2 * p][1] = r1;
                bh[2 * p + 1][0] = r2; bh[2 * p + 1][1] = r3;
                ldsm4(r0, r1, r2, r3, st + 32768u + off);
                bl[2 * p][0] = r0; bl[2 * p][1] = r1;
                bl[2 * p + 1][0] = r2; bl[2 * p + 1][1] = r3;
            }
            // 2-product split: ah*bh + ah*bl = ah*(bh+bl); dropped xl*W ~ 2^-11
            #pragma unroll
            for (int mi = 0; mi < 4; mi++)
                #pragma unroll
                for (int ni = 0; ni < 4; ni++) {
                    mma16816(acc[mi][ni], ah[mi], bh[ni]);
                    mma16816(acc[mi][ni], ah[mi], bl[ni]);
                }
        }
        __syncthreads();
        if (cc + 3 < NCH)
            load_stage(sb + (uint32_t)((cc + 3) % NSTG) * STAGE, m0, n0, (cc + 3) * TK, tid);
    }

    // Epilogue: direct float2 stores to g_gx
    #pragma unroll
    for (int mi = 0; mi < 4; mi++) {
        int row = m0 + wm * 64 + mi * 16 + (lane >> 2);
        #pragma unroll
        for (int ni = 0; ni < 4; ni++) {
            int col = n0 + wn * 32 + ni * 8 + 2 * (lane & 3);
            *(float2*)(g_gx + (size_t)row * N3_ + col) =
                make_float2(acc[mi][ni][0], acc[mi][ni][1]);
            *(float2*)(g_gx + (size_t)(row + 8) * N3_ + col) =
                make_float2(acc[mi][ni][2], acc[mi][ni][3]);
        }
    }
}

// ---------------- IndGRU recurrence ----------------
// ILP=1, 64 blocks x 256 threads => 8 warps/block = 2 warps per SMSP, so each
// scheduler has a second warp to fill the serial chain's dependency bubbles
// (R11's ILP=2 @ 1 warp/SMSP showed chains do NOT overlap within one warp).
// Gates arrive pre-scaled from the GEMM (W rows scaled by -log2e / +2log2e),
// so the step body is pure chain + 3 cp4 + 3 LDS + 1 STG.
//   r = rcp(1 + ex2(wr'*h + gr'))            wr' = -log2e*wr
//   q = rcp(1 + ex2(gn' + r*(wn'*h)))        wn' = 2log2e*wn
//   h' = fma(-2(1-z), q, fma(z, h, 1-z))
__global__ __launch_bounds__(256) void recur_kernel(const float* __restrict__ h0,
                                                    const float* __restrict__ whh,
                                                    float* __restrict__ out) {
    constexpr int SLOTS = 16, DEPTH = 15;
    constexpr int STRIDE = B_ * N3_;               // floats per timestep in g_gx

    __shared__ float buf[SLOTS * 3 * 256];         // slot 3072B; gate stride 1024B

    int tid = threadIdx.x;
    int idx = blockIdx.x * 256 + tid;              // 0..16383 = b*512 + h
    int h = idx & (H_ - 1);
    int b = idx >> 9;

    float hv   = h0[idx];
    float wrp  = -L2E_ * whh[h];
    float wzp  = -L2E_ * whh[H_ + h];
    float wnp2 = 2.f * L2E_ * whh[2 * H_ + h];

    const float* gp = g_gx + (size_t)b * N3_ + h;  // row t*32+b, col h
    float* op = out + idx;

    uint32_t sbase = smem_u32(buf) + (uint32_t)tid * 4u;

    // Prime: timesteps 0..DEPTH-1, one commit group per timestep (3 cp4 each).
    #pragma unroll
    for (int s = 0; s < DEPTH; s++) {
        uint32_t sa = sbase + (uint32_t)s * 3072u;
        cp4(sa,          gp);
        cp4(sa + 1024u,  gp + H_);
        cp4(sa + 2048u,  gp + 2 * H_);
        cp_commit();
        gp += STRIDE;
    }

    asm volatile("cp.async.wait_group 14;" ::: "memory");
    float cr = lds1(sbase), cz = lds1(sbase + 1024u), cn = lds1(sbase + 2048u);

    for (int t = 0; t < T_; t++) {
        asm volatile("cp.async.wait_group 13;" ::: "memory");
        int tn = (t + 1 < T_) ? t + 1 : t;
        uint32_t na = sbase + (uint32_t)((tn & (SLOTS - 1)) * 3072);
        float nr = lds1(na), nz = lds1(na + 1024u), nn = lds1(na + 2048u);

        // Serial chain on timestep t (gates pre-scaled).
        float er = ex2f(fmaf(wrp, hv, cr));
        float ez = ex2f(fmaf(wzp, hv, cz));
        float r  = rcpf(1.f + er);
        float z  = rcpf(1.f + ez);
        float en = ex2f(fmaf(r, wnp2 * hv, cn));
        float q  = rcpf(1.f + en);
        float omz = 1.f - z;
        hv = fmaf(-2.f * omz, q, fmaf(z, hv, omz));   // (1-z)(1-2q) + z*h
        *op = hv;
        op += B_ * H_;

        // Refill slot (t+DEPTH)%16 = (t-1)%16 (already consumed).
        if (t + DEPTH < T_) {
            uint32_t wa = sbase + (uint32_t)(((t + DEPTH) & (SLOTS - 1)) * 3072);
            cp4(wa,          gp);
            cp4(wa + 1024u,  gp + H_);
            cp4(wa + 2048u,  gp + 2 * H_);
            gp += STRIDE;
        }
        cp_commit();                               // group g == timestep g, always
        cr = nr; cz = nz; cn = nn;
    }
    out[(size_t)T_ * B_ * H_ + idx] = hv;          // h_last
}

// ---------------- launch ----------------
extern "C" void kernel_launch(void* const* d_in, const int* in_sizes, int n_in,
                              void* d_out, int out_size) {
    const float* x   = (const float*)d_in[0];   // (T, B, I)
    const float* h0  = (const float*)d_in[1];   // (B, H)
    const float* Wih = (const float*)d_in[2];   // (3H, I)
    const float* whh = (const float*)d_in[3];   // (3, H)
    float* out = (float*)d_out;                 // (T,B,H) then (1,B,H)

    (void)in_sizes; (void)n_in; (void)out_size;

    cudaFuncSetAttribute(gemm_kernel, cudaFuncAttributeMaxDynamicSharedMemorySize, SMEM_TOTAL);

    split_x_kernel<<<(M_ * K_ / 4) / 256, 256>>>(x);
    split_w_kernel<<<(N3_ * K_ / 4) / 256, 256>>>(Wih);
    gemm_kernel<<<dim3(M_ / TM, N3_ / TN), 256, SMEM_TOTAL>>>();
    recur_kernel<<<64, 256>>>(h0, whh, out);
}

// round 15
// speedup vs baseline: 2.4043x; 1.3617x over previous
#include <cuda_runtime.h>
#include <cuda_fp16.h>
#include <cstdint>

// Problem dims
static constexpr int T_ = 512, B_ = 32, I_ = 512, H_ = 512;
static constexpr int M_  = T_ * B_;   // 16384 (GEMM M)
static constexpr int N3_ = 3 * H_;    // 1536  (GEMM N)
static constexpr int K_  = I_;        // 512   (GEMM K)

// GEMM tiling (mma.sync m16n8k16, baseline sm_103 features only — NO tcgen05)
static constexpr int TM = 128, TN = 128, TK = 64;
static constexpr int NCH  = K_ / TK;        // 8 K-tiles
static constexpr int NSTG = 4;
// Stage: Ah 16K | Bh 16K  (each 128 rows x 128B swizzled)
static constexpr int STAGE = 32768;
static constexpr int SMEM_TOTAL = NSTG * STAGE;   // 131072

// ---------------- scratch (device globals; no allocation allowed) ----------------
__device__ __align__(256) __half g_xh[(size_t)M_ * K_];
__device__ __align__(256) __half g_wh[(size_t)N3_ * K_];
__device__ __align__(256) float  g_gx[(size_t)M_ * N3_];

// ---------------- PTX helpers (all baseline sm_80+ features) ----------------
__device__ __forceinline__ uint32_t smem_u32(const void* p) {
    return (uint32_t)__cvta_generic_to_shared(p);
}
__device__ __forceinline__ void cp16(uint32_t s, const void* g) {
    asm volatile("cp.async.cg.shared.global [%0], [%1], 16;" :: "r"(s), "l"(g));
}
__device__ __forceinline__ void cp4(uint32_t s, const void* g) {
    asm volatile("cp.async.ca.shared.global [%0], [%1], 4;" :: "r"(s), "l"(g));
}
__device__ __forceinline__ void cp_commit() {
    asm volatile("cp.async.commit_group;" ::: "memory");
}
__device__ __forceinline__ void ldsm4(uint32_t& r0, uint32_t& r1, uint32_t& r2, uint32_t& r3,
                                      uint32_t a) {
    asm volatile("ldmatrix.sync.aligned.m8n8.x4.shared.b16 {%0,%1,%2,%3}, [%4];"
                 : "=r"(r0), "=r"(r1), "=r"(r2), "=r"(r3) : "r"(a));
}
__device__ __forceinline__ void mma16816(float* c, const uint32_t* a, const uint32_t* b) {
    asm volatile(
        "mma.sync.aligned.m16n8k16.row.col.f32.f16.f16.f32 "
        "{%0,%1,%2,%3}, {%4,%5,%6,%7}, {%8,%9}, {%0,%1,%2,%3};"
        : "+f"(c[0]), "+f"(c[1]), "+f"(c[2]), "+f"(c[3])
        : "r"(a[0]), "r"(a[1]), "r"(a[2]), "r"(a[3]), "r"(b[0]), "r"(b[1]));
}
__device__ __forceinline__ float ex2f(float x) {
    float y; asm("ex2.approx.f32 %0, %1;" : "=f"(y) : "f"(x)); return y;
}
__device__ __forceinline__ float rcpf(float x) {
    float y; asm("rcp.approx.f32 %0, %1;" : "=f"(y) : "f"(x)); return y;
}
__device__ __forceinline__ float lds1(uint32_t a) {
    float v; asm volatile("ld.shared.f32 %0, [%1];" : "=f"(v) : "r"(a)); return v;
}

// ---------------- prep ----------------
static constexpr float L2E_ = 1.4426950408889634f;

// x: fp16 hi (dropped x_lo contributes ~2^-12 relative, measured 2.5e-4 final)
__global__ void split_x_kernel(const float* __restrict__ src) {
    int i = blockIdx.x * blockDim.x + threadIdx.x;          // one float4 per thread
    float4 v = ((const float4*)src)[i];
    __half2* ph = (__half2*)g_xh;
    ph[2 * i]     = __halves2half2(__float2half_rn(v.x), __float2half_rn(v.y));
    ph[2 * i + 1] = __halves2half2(__float2half_rn(v.z), __float2half_rn(v.w));
}

// W rows pre-scaled per gate so gx arrives activation-ready:
//   r,z rows * (-log2e);  n rows * (+2 log2e). Single fp16 (w_lo dropped:
//   adds an independent ~2.5e-4 error component; total ~4e-4 < 1e-3 gate).
__global__ void split_w_kernel(const float* __restrict__ src) {
    int i = blockIdx.x * blockDim.x + threadIdx.x;
    int row = i >> 7;                                       // (i*4)/K_
    float sc = (row >= 2 * H_) ? (2.f * L2E_) : (-L2E_);
    float4 v = ((const float4*)src)[i];
    __half2* ph = (__half2*)g_wh;
    ph[2 * i]     = __halves2half2(__float2half_rn(v.x * sc), __float2half_rn(v.y * sc));
    ph[2 * i + 1] = __halves2half2(__float2half_rn(v.z * sc), __float2half_rn(v.w * sc));
}

// ---------------- GEMM: gx = xh @ wh^T via mma.sync (single product) -------------
// Smem row layout: 64 fp16 = 128B per row; 16B chunk j stored at (j ^ (row&7))*16.
__device__ __forceinline__ void load_quarter(uint32_t dst, const __half* __restrict__ g,
                                             int row0, int k0, int tid) {
    // 128 rows x 8 chunks of 16B = 1024 cp16, 256 threads -> 4 each
    #pragma unroll
    for (int u = 0; u < 4; u++) {
        int i = tid + u * 256;
        int r = i >> 3, j = i & 7;
        cp16(dst + (uint32_t)(r * 128 + ((j ^ (r & 7)) << 4)),
             g + (size_t)(row0 + r) * K_ + k0 + j * 8);
    }
}

__device__ __forceinline__ void load_stage(uint32_t st, int m0, int n0, int k0, int tid) {
    load_quarter(st,          g_xh, m0, k0, tid);
    load_quarter(st + 16384u, g_wh, n0, k0, tid);
    cp_commit();
}

__global__ __launch_bounds__(256, 1) void gemm_kernel() {
    extern __shared__ __align__(1024) char smem[];
    uint32_t sb = smem_u32(smem);
    int tid = threadIdx.x, lane = tid & 31, wid = tid >> 5;
    int wm = wid & 1, wn = wid >> 1;          // 2 x 4 warp grid; warp tile 64m x 32n
    int m0 = blockIdx.x * TM, n0 = blockIdx.y * TN;
    int g = lane >> 3;                         // ldmatrix lane group

    float acc[4][4][4];
    #pragma unroll
    for (int a = 0; a < 4; a++)
        #pragma unroll
        for (int b = 0; b < 4; b++)
            #pragma unroll
            for (int c = 0; c < 4; c++) acc[a][b][c] = 0.f;

    load_stage(sb,             m0, n0, 0,      tid);
    load_stage(sb + STAGE,     m0, n0, TK,     tid);
    load_stage(sb + 2 * STAGE, m0, n0, 2 * TK, tid);

    for (int cc = 0; cc < NCH; cc++) {
        if (cc < 6)       asm volatile("cp.async.wait_group 2;" ::: "memory");
        else if (cc == 6) asm volatile("cp.async.wait_group 1;" ::: "memory");
        else              asm volatile("cp.async.wait_group 0;" ::: "memory");
        __syncthreads();

        uint32_t st = sb + (uint32_t)(cc % NSTG) * STAGE;
        #pragma unroll
        for (int ks = 0; ks < 4; ks++) {
            // A fragments: 4 m-frags of 16 rows each
            uint32_t ah[4][4];
            #pragma unroll
            for (int mi = 0; mi < 4; mi++) {
                int row = wm * 64 + mi * 16 + ((g & 1) << 3) + (lane & 7);
                uint32_t off = (uint32_t)(row * 128 +
                                (((ks * 2 + (g >> 1)) ^ (row & 7)) << 4));
                ldsm4(ah[mi][0], ah[mi][1], ah[mi][2], ah[mi][3], st + off);
            }
            // B fragments: 4 n-frags of 8, loaded in pairs via x4
            uint32_t bh[4][2];
            #pragma unroll
            for (int p = 0; p < 2; p++) {
                int row = wn * 32 + p * 16 + ((g >> 1) << 3) + (lane & 7);
                uint32_t off = (uint32_t)(row * 128 +
                                (((ks * 2 + (g & 1)) ^ (row & 7)) << 4));
                uint32_t r0, r1, r2, r3;
                ldsm4(r0, r1, r2, r3, st + 16384u + off);
                bh[2 * p][0] = r0; bh[2 * p][1] = r1;
                bh[2 * p + 1][0] = r2; bh[2 * p + 1][1] = r3;
            }
            #pragma unroll
            for (int mi = 0; mi < 4; mi++)
                #pragma unroll
                for (int ni = 0; ni < 4; ni++)
                    mma16816(acc[mi][ni], ah[mi], bh[ni]);
        }
        __syncthreads();
        if (cc + 3 < NCH)
            load_stage(sb + (uint32_t)((cc + 3) % NSTG) * STAGE, m0, n0, (cc + 3) * TK, tid);
    }

    // Epilogue: direct float2 stores to g_gx
    #pragma unroll
    for (int mi = 0; mi < 4; mi++) {
        int row = m0 + wm * 64 + mi * 16 + (lane >> 2);
        #pragma unroll
        for (int ni = 0; ni < 4; ni++) {
            int col = n0 + wn * 32 + ni * 8 + 2 * (lane & 3);
            *(float2*)(g_gx + (size_t)row * N3_ + col) =
                make_float2(acc[mi][ni][0], acc[mi][ni][1]);
            *(float2*)(g_gx + (size_t)(row + 8) * N3_ + col) =
                make_float2(acc[mi][ni][2], acc[mi][ni][3]);
        }
    }
}

// ---------------- IndGRU recurrence ----------------
// R9's best config (128 blocks x 128 threads: max SM coverage; 512 warps can't
// fill 592 schedulers, so SM count > per-scheduler depth — R12 measured this).
// Gates arrive pre-scaled from the GEMM (W rows scaled by -log2e / +2log2e).
// SMEM cp.async prefetch ring: 16 slots, DEPTH=15, group g == timestep g;
// wait_group 13 at iter t makes timestep t+1 resident (LDS off the chain).
//   r = rcp(1 + ex2(wr'*h + gr'))            wr' = -log2e*wr
//   q = rcp(1 + ex2(gn' + r*(wn'*h)))        wn' = 2log2e*wn
//   h' = fma(-2(1-z), q, fma(z, h, 1-z))
__global__ __launch_bounds__(128) void recur_kernel(const float* __restrict__ h0,
                                                    const float* __restrict__ whh,
                                                    float* __restrict__ out) {
    constexpr int SLOTS = 16, DEPTH = 15;
    constexpr int STRIDE = B_ * N3_;               // floats per timestep in g_gx

    __shared__ float buf[SLOTS * 3 * 128];         // slot 1536B; gate stride 512B

    int tid = threadIdx.x;
    int idx = blockIdx.x * 128 + tid;              // 0..16383 = b*512 + h
    int h = idx & (H_ - 1);
    int b = idx >> 9;

    float hv   = h0[idx];
    float wrp  = -L2E_ * whh[h];
    float wzp  = -L2E_ * whh[H_ + h];
    float wnp2 = 2.f * L2E_ * whh[2 * H_ + h];

    const float* gp = g_gx + (size_t)b * N3_ + h;  // row t*32+b, col h
    float* op = out + idx;

    uint32_t sbase = smem_u32(buf) + (uint32_t)tid * 4u;

    // Prime: timesteps 0..DEPTH-1, one commit group per timestep (3 cp4 each).
    #pragma unroll
    for (int s = 0; s < DEPTH; s++) {
        uint32_t sa = sbase + (uint32_t)s * 1536u;
        cp4(sa,         gp);
        cp4(sa + 512u,  gp + H_);
        cp4(sa + 1024u, gp + 2 * H_);
        cp_commit();
        gp += STRIDE;
    }

    asm volatile("cp.async.wait_group 14;" ::: "memory");
    float cr = lds1(sbase), cz = lds1(sbase + 512u), cn = lds1(sbase + 1024u);

    for (int t = 0; t < T_; t++) {
        asm volatile("cp.async.wait_group 13;" ::: "memory");
        int tn = (t + 1 < T_) ? t + 1 : t;
        uint32_t na = sbase + (uint32_t)((tn & (SLOTS - 1)) * 1536);
        float nr = lds1(na), nz = lds1(na + 512u), nn = lds1(na + 1024u);

        // Serial chain on timestep t (gates pre-scaled).
        float er = ex2f(fmaf(wrp, hv, cr));
        float ez = ex2f(fmaf(wzp, hv, cz));
        float r  = rcpf(1.f + er);
        float z  = rcpf(1.f + ez);
        float en = ex2f(fmaf(r, wnp2 * hv, cn));
        float q  = rcpf(1.f + en);
        float omz = 1.f - z;
        hv = fmaf(-2.f * omz, q, fmaf(z, hv, omz));   // (1-z)(1-2q) + z*h
        *op = hv;
        op += B_ * H_;

        // Refill slot (t+DEPTH)%16 = (t-1)%16 (already consumed).
        if (t + DEPTH < T_) {
            uint32_t wa = sbase + (uint32_t)(((t + DEPTH) & (SLOTS - 1)) * 1536);
            cp4(wa,         gp);
            cp4(wa + 512u,  gp + H_);
            cp4(wa + 1024u, gp + 2 * H_);
            gp += STRIDE;
        }
        cp_commit();                               // group g == timestep g, always
        cr = nr; cz = nz; cn = nn;
    }
    out[(size_t)T_ * B_ * H_ + idx] = hv;          // h_last
}

// ---------------- launch ----------------
extern "C" void kernel_launch(void* const* d_in, const int* in_sizes, int n_in,
                              void* d_out, int out_size) {
    const float* x   = (const float*)d_in[0];   // (T, B, I)
    const float* h0  = (const float*)d_in[1];   // (B, H)
    const float* Wih = (const float*)d_in[2];   // (3H, I)
    const float* whh = (const float*)d_in[3];   // (3, H)
    float* out = (float*)d_out;                 // (T,B,H) then (1,B,H)

    (void)in_sizes; (void)n_in; (void)out_size;

    cudaFuncSetAttribute(gemm_kernel, cudaFuncAttributeMaxDynamicSharedMemorySize, SMEM_TOTAL);

    split_x_kernel<<<(M_ * K_ / 4) / 256, 256>>>(x);
    split_w_kernel<<<(N3_ * K_ / 4) / 256, 256>>>(Wih);
    gemm_kernel<<<dim3(M_ / TM, N3_ / TN), 256, SMEM_TOTAL>>>();
    recur_kernel<<<128, 128>>>(h0, whh, out);
}

// round 17
// speedup vs baseline: 2.4562x; 1.0216x over previous
#include <cuda_runtime.h>
#include <cuda_fp16.h>
#include <cstdint>

// Problem dims
static constexpr int T_ = 512, B_ = 32, I_ = 512, H_ = 512;
static constexpr int M_  = T_ * B_;   // 16384 (GEMM M)
static constexpr int N3_ = 3 * H_;    // 1536  (GEMM N)
static constexpr int K_  = I_;        // 512   (GEMM K)

// GEMM tiling (mma.sync m16n8k16, baseline sm_103 features only — NO tcgen05)
static constexpr int TM = 128, TN = 128, TK = 64;
static constexpr int NCH  = K_ / TK;        // 8 K-tiles
static constexpr int NT_M = M_ / TM;        // 128 m-tiles
static constexpr int NT_N = N3_ / TN;       // 12 n-tiles
// 2-stage pipeline: Ah 16K | Bh 16K per stage -> 64KB dynamic smem
static constexpr int STAGE = 32768;
static constexpr int SMEM_TOTAL = 2 * STAGE;      // 65536

// ---------------- scratch (device globals; no allocation allowed) ----------------
__device__ __align__(256) __half g_xh[(size_t)M_ * K_];
__device__ __align__(256) __half g_wh[(size_t)N3_ * K_];
__device__ __align__(256) float  g_gx[(size_t)M_ * N3_];
__device__ int g_tile_done[NT_M];   // n-tiles completed per m-tile (0..12)

// ---------------- PTX helpers (all baseline sm_80+ features) ----------------
__device__ __forceinline__ uint32_t smem_u32(const void* p) {
    return (uint32_t)__cvta_generic_to_shared(p);
}
__device__ __forceinline__ void cp16(uint32_t s, const void* g) {
    asm volatile("cp.async.cg.shared.global [%0], [%1], 16;" :: "r"(s), "l"(g));
}
__device__ __forceinline__ void cp4(uint32_t s, const void* g) {
    asm volatile("cp.async.ca.shared.global [%0], [%1], 4;" :: "r"(s), "l"(g));
}
__device__ __forceinline__ void cp_commit() {
    asm volatile("cp.async.commit_group;" ::: "memory");
}
__device__ __forceinline__ void ldsm4(uint32_t& r0, uint32_t& r1, uint32_t& r2, uint32_t& r3,
                                      uint32_t a) {
    asm volatile("ldmatrix.sync.aligned.m8n8.x4.shared.b16 {%0,%1,%2,%3}, [%4];"
                 : "=r"(r0), "=r"(r1), "=r"(r2), "=r"(r3) : "r"(a));
}
__device__ __forceinline__ void mma16816(float* c, const uint32_t* a, const uint32_t* b) {
    asm volatile(
        "mma.sync.aligned.m16n8k16.row.col.f32.f16.f16.f32 "
        "{%0,%1,%2,%3}, {%4,%5,%6,%7}, {%8,%9}, {%0,%1,%2,%3};"
        : "+f"(c[0]), "+f"(c[1]), "+f"(c[2]), "+f"(c[3])
        : "r"(a[0]), "r"(a[1]), "r"(a[2]), "r"(a[3]), "r"(b[0]), "r"(b[1]));
}
__device__ __forceinline__ float ex2f(float x) {
    float y; asm("ex2.approx.f32 %0, %1;" : "=f"(y) : "f"(x)); return y;
}
__device__ __forceinline__ float rcpf(float x) {
    float y; asm("rcp.approx.f32 %0, %1;" : "=f"(y) : "f"(x)); return y;
}
__device__ __forceinline__ float lds1(uint32_t a) {
    float v; asm volatile("ld.shared.f32 %0, [%1];" : "=f"(v) : "r"(a)); return v;
}
__device__ __forceinline__ void wait_tile(int tile) {
    for (;;) {
        int v;
        asm volatile("ld.acquire.gpu.b32 %0, [%1];" : "=r"(v) : "l"(g_tile_done + tile));
        if (v >= NT_N) break;
        asm volatile("nanosleep.u32 128;");
    }
}

// ---------------- prep ----------------
static constexpr float L2E_ = 1.4426950408889634f;

// x: fp16 hi (dropped x_lo contributes ~2.5e-4 final). Also zeroes the
// producer-consumer tile flags for the fused kernel (runs before it on-stream).
__global__ void split_x_kernel(const float* __restrict__ src) {
    if (blockIdx.x == 0 && threadIdx.x < NT_M) g_tile_done[threadIdx.x] = 0;
    int i = blockIdx.x * blockDim.x + threadIdx.x;          // one float4 per thread
    float4 v = ((const float4*)src)[i];
    __half2* ph = (__half2*)g_xh;
    ph[2 * i]     = __halves2half2(__float2half_rn(v.x), __float2half_rn(v.y));
    ph[2 * i + 1] = __halves2half2(__float2half_rn(v.z), __float2half_rn(v.w));
}

// W rows pre-scaled per gate so gx arrives activation-ready:
//   r,z rows * (-log2e);  n rows * (+2 log2e). Single fp16 (w_lo dropped).
__global__ void split_w_kernel(const float* __restrict__ src) {
    int i = blockIdx.x * blockDim.x + threadIdx.x;
    int row = i >> 7;                                       // (i*4)/K_
    float sc = (row >= 2 * H_) ? (2.f * L2E_) : (-L2E_);
    float4 v = ((const float4*)src)[i];
    __half2* ph = (__half2*)g_wh;
    ph[2 * i]     = __halves2half2(__float2half_rn(v.x * sc), __float2half_rn(v.y * sc));
    ph[2 * i + 1] = __halves2half2(__float2half_rn(v.z * sc), __float2half_rn(v.w * sc));
}

// ---------------- GEMM body: gx = xh @ wh^T (single fp16 product) ----------------
// Smem row layout: 64 fp16 = 128B per row; 16B chunk j stored at (j ^ (row&7))*16.
__device__ __forceinline__ void load_quarter(uint32_t dst, const __half* __restrict__ g,
                                             int row0, int k0, int tid) {
    #pragma unroll
    for (int u = 0; u < 4; u++) {
        int i = tid + u * 256;
        int r = i >> 3, j = i & 7;
        cp16(dst + (uint32_t)(r * 128 + ((j ^ (r & 7)) << 4)),
             g + (size_t)(row0 + r) * K_ + k0 + j * 8);
    }
}

__device__ __forceinline__ void load_stage(uint32_t st, int m0, int n0, int k0, int tid) {
    load_quarter(st,          g_xh, m0, k0, tid);
    load_quarter(st + 16384u, g_wh, n0, k0, tid);
    cp_commit();
}

__device__ __forceinline__ void gemm_body(char* smem, int idx) {
    uint32_t sb = smem_u32(smem);
    int tid = threadIdx.x, lane = tid & 31, wid = tid >> 5;
    int wm = wid & 1, wn = wid >> 1;          // 2 x 4 warp grid; warp tile 64m x 32n
    int mt = idx / NT_N, nt = idx % NT_N;     // m-tile-major: early timesteps first
    int m0 = mt * TM, n0 = nt * TN;
    int g = lane >> 3;                         // ldmatrix lane group

    float acc[4][4][4];
    #pragma unroll
    for (int a = 0; a < 4; a++)
        #pragma unroll
        for (int b = 0; b < 4; b++)
            #pragma unroll
            for (int c = 0; c < 4; c++) acc[a][b][c] = 0.f;

    load_stage(sb,         m0, n0, 0,  tid);
    load_stage(sb + STAGE, m0, n0, TK, tid);

    for (int cc = 0; cc < NCH; cc++) {
        if (cc < NCH - 1) asm volatile("cp.async.wait_group 1;" ::: "memory");
        else              asm volatile("cp.async.wait_group 0;" ::: "memory");
        __syncthreads();

        uint32_t st = sb + (uint32_t)(cc & 1) * STAGE;
        #pragma unroll
        for (int ks = 0; ks < 4; ks++) {
            uint32_t ah[4][4];
            #pragma unroll
            for (int mi = 0; mi < 4; mi++) {
                int row = wm * 64 + mi * 16 + ((g & 1) << 3) + (lane & 7);
                uint32_t off = (uint32_t)(row * 128 +
                                (((ks * 2 + (g >> 1)) ^ (row & 7)) << 4));
                ldsm4(ah[mi][0], ah[mi][1], ah[mi][2], ah[mi][3], st + off);
            }
            uint32_t bh[4][2];
            #pragma unroll
            for (int p = 0; p < 2; p++) {
                int row = wn * 32 + p * 16 + ((g >> 1) << 3) + (lane & 7);
                uint32_t off = (uint32_t)(row * 128 +
                                (((ks * 2 + (g & 1)) ^ (row & 7)) << 4));
                uint32_t r0, r1, r2, r3;
                ldsm4(r0, r1, r2, r3, st + 16384u + off);
                bh[2 * p][0] = r0; bh[2 * p][1] = r1;
                bh[2 * p + 1][0] = r2; bh[2 * p + 1][1] = r3;
            }
            #pragma unroll
            for (int mi = 0; mi < 4; mi++)
                #pragma unroll
                for (int ni = 0; ni < 4; ni++)
                    mma16816(acc[mi][ni], ah[mi], bh[ni]);
        }
        __syncthreads();
        if (cc + 2 < NCH)
            load_stage(sb + (uint32_t)(cc & 1) * STAGE, m0, n0, (cc + 2) * TK, tid);
    }

    // Epilogue: direct float2 stores to g_gx
    #pragma unroll
    for (int mi = 0; mi < 4; mi++) {
        int row = m0 + wm * 64 + mi * 16 + (lane >> 2);
        #pragma unroll
        for (int ni = 0; ni < 4; ni++) {
            int col = n0 + wn * 32 + ni * 8 + 2 * (lane & 3);
            *(float2*)(g_gx + (size_t)row * N3_ + col) =
                make_float2(acc[mi][ni][0], acc[mi][ni][1]);
            *(float2*)(g_gx + (size_t)(row + 8) * N3_ + col) =
                make_float2(acc[mi][ni][2], acc[mi][ni][3]);
        }
    }
    // Publish: every thread fences its own stores, then one thread signals.
    __threadfence();
    __syncthreads();
    if (tid == 0) atomicAdd(&g_tile_done[mt], 1);
}

// ---------------- recurrence body (blocks 0..127, threads 0..127) ----------------
// m-tile mt covers timesteps 4mt..4mt+3; every prefetch cp.async for timestep s
// is gated on tile_done[s/4] == 12 (acquire), so the recurrence chases the GEMM
// frontier and overlaps with it. Ring/math identical to the proven R15 kernel.
__device__ __forceinline__ void recur_body(char* smemc, const float* __restrict__ h0,
                                           const float* __restrict__ whh,
                                           float* __restrict__ out) {
    constexpr int SLOTS = 16, DEPTH = 15;
    constexpr int STRIDE = B_ * N3_;               // floats per timestep in g_gx
    float* buf = (float*)smemc;                    // 16 slots x 3 gates x 128 thr

    int tid = threadIdx.x;
    int idx = blockIdx.x * 128 + tid;              // 0..16383 = b*512 + h
    int h = idx & (H_ - 1);
    int b = idx >> 9;

    float hv   = h0[idx];
    float wrp  = -L2E_ * whh[h];
    float wzp  = -L2E_ * whh[H_ + h];
    float wnp2 = 2.f * L2E_ * whh[2 * H_ + h];

    const float* gp = g_gx + (size_t)b * N3_ + h;  // row t*32+b, col h
    float* op = out + idx;

    uint32_t sbase = smem_u32(buf) + (uint32_t)tid * 4u;

    // Prime: timesteps 0..DEPTH-1, one commit group per timestep (3 cp4 each).
    #pragma unroll
    for (int s = 0; s < DEPTH; s++) {
        if ((s & 3) == 0) wait_tile(s >> 2);
        uint32_t sa = sbase + (uint32_t)s * 1536u;
        cp4(sa,         gp);
        cp4(sa + 512u,  gp + H_);
        cp4(sa + 1024u, gp + 2 * H_);
        cp_commit();
        gp += STRIDE;
    }

    asm volatile("cp.async.wait_group 14;" ::: "memory");
    float cr = lds1(sbase), cz = lds1(sbase + 512u), cn = lds1(sbase + 1024u);

    for (int t = 0; t < T_; t++) {
        asm volatile("cp.async.wait_group 13;" ::: "memory");
        int tn = (t + 1 < T_) ? t + 1 : t;
        uint32_t na = sbase + (uint32_t)((tn & (SLOTS - 1)) * 1536);
        float nr = lds1(na), nz = lds1(na + 512u), nn = lds1(na + 1024u);

        // Serial chain on timestep t (gates pre-scaled).
        float er = ex2f(fmaf(wrp, hv, cr));
        float ez = ex2f(fmaf(wzp, hv, cz));
        float r  = rcpf(1.f + er);
        float z  = rcpf(1.f + ez);
        float en = ex2f(fmaf(r, wnp2 * hv, cn));
        float q  = rcpf(1.f + en);
        float omz = 1.f - z;
        hv = fmaf(-2.f * omz, q, fmaf(z, hv, omz));   // (1-z)(1-2q) + z*h
        *op = hv;
        op += B_ * H_;

        // Refill slot (t+DEPTH)%16 = (t-1)%16 (already consumed).
        if (t + DEPTH < T_) {
            int s = t + DEPTH;
            if ((s & 3) == 0) wait_tile(s >> 2);
            uint32_t wa = sbase + (uint32_t)((s & (SLOTS - 1)) * 1536);
            cp4(wa,         gp);
            cp4(wa + 512u,  gp + H_);
            cp4(wa + 1024u, gp + 2 * H_);
            gp += STRIDE;
        }
        cp_commit();                               // group g == timestep g, always
        cr = nr; cz = nz; cn = nn;
    }
    out[(size_t)T_ * B_ * H_ + idx] = hv;          // h_last
}

// ---------------- fused kernel: recur blocks first, then GEMM (m-major) ----------
__global__ __launch_bounds__(256, 2) void fused_kernel(const float* __restrict__ h0,
                                                       const float* __restrict__ whh,
                                                       float* __restrict__ out) {
    extern __shared__ __align__(1024) char smem[];
    if (blockIdx.x < 128) {
        if (threadIdx.x < 128) recur_body(smem, h0, whh, out);
        return;
    }
    gemm_body(smem, blockIdx.x - 128);
}

// ---------------- launch ----------------
extern "C" void kernel_launch(void* const* d_in, const int* in_sizes, int n_in,
                              void* d_out, int out_size) {
    const float* x   = (const float*)d_in[0];   // (T, B, I)
    const float* h0  = (const float*)d_in[1];   // (B, H)
    const float* Wih = (const float*)d_in[2];   // (3H, I)
    const float* whh = (const float*)d_in[3];   // (3, H)
    float* out = (float*)d_out;                 // (T,B,H) then (1,B,H)

    (void)in_sizes; (void)n_in; (void)out_size;

    cudaFuncSetAttribute(fused_kernel, cudaFuncAttributeMaxDynamicSharedMemorySize,
                         SMEM_TOTAL);

    split_x_kernel<<<(M_ * K_ / 4) / 256, 256>>>(x);
    split_w_kernel<<<(N3_ * K_ / 4) / 256, 256>>>(Wih);
    fused_kernel<<<128 + NT_M * NT_N, 256, SMEM_TOTAL>>>(h0, whh, out);
}